// round 1
// baseline (speedup 1.0000x reference)
#include <cuda_runtime.h>
#include <cstdint>

#define DD 256
#define MT 64      // rows per block
#define KT 16      // k-tile

typedef unsigned long long ull;

__device__ __forceinline__ void ffma2(ull& d, ull a, ull b) {
    asm volatile("fma.rn.f32x2 %0, %1, %2, %0;" : "+l"(d) : "l"(a), "l"(b));
}
__device__ __forceinline__ unsigned smem_u32(const void* p) {
    return (unsigned)__cvta_generic_to_shared(p);
}
__device__ __forceinline__ void cp_async16(unsigned s, const void* g) {
    asm volatile("cp.async.cg.shared.global [%0], [%1], 16;" :: "r"(s), "l"(g));
}
__device__ __forceinline__ void cp_commit() { asm volatile("cp.async.commit_group;"); }
__device__ __forceinline__ void cp_wait0() { asm volatile("cp.async.wait_group 0;" ::: "memory"); }

// smem layout (floats):
// hdup  [0, 32768)           64 rows x 512 (each h value duplicated -> f32x2 loads)
// w2s   [32768, 40960)       2 bufs x 16x256
// w1s   [40960, 43520)       10x256
// b1s   [43520, 43776)
// gms   [43776, 44032)
// bts   [44032, 44288)
// b2s   [44288, 44544)
// lfws  [44544, 49664)       256 x 20 (18 used + 2 pad for float4 loads)
// lfbs  [49664, 49696)
#define SMEM_FLOATS 49696

__global__ void __launch_bounds__(256, 1)
gauss_fused_kernel(const float* __restrict__ mu, const float* __restrict__ sc,
                   const float* __restrict__ rot, const float* __restrict__ Q,
                   const float* __restrict__ w1, const float* __restrict__ b1,
                   const float* __restrict__ gamma, const float* __restrict__ beta,
                   const float* __restrict__ w2, const float* __restrict__ b2,
                   const float* __restrict__ lfw, const float* __restrict__ lfb,
                   float* __restrict__ out, int N)
{
    extern __shared__ float sm[];
    float* hdup = sm;
    float* w2s  = sm + 32768;
    float* w1s  = sm + 40960;
    float* b1s  = sm + 43520;
    float* gms  = sm + 43776;
    float* bts  = sm + 44032;
    float* b2s  = sm + 44288;
    float* lfws = sm + 44544;
    float* lfbs = sm + 49664;

    const int tid  = threadIdx.x;
    const int lane = tid & 31;
    const int wrp  = tid >> 5;
    const int rowBase = blockIdx.x * MT;

    // ---- stage constants into smem ----
    #pragma unroll
    for (int i = tid; i < 2560; i += 256) w1s[i] = w1[i];
    b1s[tid] = b1[tid];
    gms[tid] = gamma[tid];
    bts[tid] = beta[tid];
    b2s[tid] = b2[tid];
    {
        const int c = tid;
        #pragma unroll
        for (int j = 0; j < 18; ++j) lfws[c*20 + j] = lfw[c*18 + j];
        lfws[c*20 + 18] = 0.f; lfws[c*20 + 19] = 0.f;
    }
    if (tid < 18) lfbs[tid] = lfb[tid];
    __syncthreads();

    // ---- phase 1: h = relu(LN(geo@w1+b1)); one warp per row ----
    #pragma unroll 1
    for (int ii = 0; ii < 8; ++ii) {
        const int rl  = wrp * 8 + ii;
        const int row = rowBase + rl;
        const bool valid = (row < N);
        float g[10];
        if (valid) {
            g[0]=mu[row*3]; g[1]=mu[row*3+1]; g[2]=mu[row*3+2];
            g[3]=sc[row*3]; g[4]=sc[row*3+1]; g[5]=sc[row*3+2];
            g[6]=rot[row*4]; g[7]=rot[row*4+1]; g[8]=rot[row*4+2]; g[9]=rot[row*4+3];
        } else {
            #pragma unroll
            for (int i = 0; i < 10; ++i) g[i] = 0.f;
        }
        float hv[8];
        float s = 0.f;
        #pragma unroll
        for (int jj = 0; jj < 8; ++jj) {
            const int d = lane + 32*jj;
            float a = b1s[d];
            #pragma unroll
            for (int i = 0; i < 10; ++i) a = fmaf(g[i], w1s[i*256 + d], a);
            hv[jj] = a; s += a;
        }
        #pragma unroll
        for (int o = 16; o; o >>= 1) s += __shfl_xor_sync(0xffffffffu, s, o);
        const float mean = s * (1.f/256.f);
        float v = 0.f;
        #pragma unroll
        for (int jj = 0; jj < 8; ++jj) { float t = hv[jj] - mean; v = fmaf(t, t, v); }
        #pragma unroll
        for (int o = 16; o; o >>= 1) v += __shfl_xor_sync(0xffffffffu, v, o);
        const float inv = rsqrtf(v * (1.f/256.f) + 1e-5f);
        #pragma unroll
        for (int jj = 0; jj < 8; ++jj) {
            const int d = lane + 32*jj;
            float t = (hv[jj] - mean) * inv * gms[d] + bts[d];
            t = fmaxf(t, 0.f);
            if (!valid) t = 0.f;
            *(float2*)&hdup[rl*512 + 2*d] = make_float2(t, t);
        }
    }
    __syncthreads();

    // ---- phase 2: E = h @ w2  (f32x2 packed FMA; 8x8 per thread) ----
    const int r0 = wrp * 8;   // thread-row base (8 rows)
    const int c0 = lane * 8;  // thread-col base (8 cols)

    ull acc[8][4];
    #pragma unroll
    for (int i = 0; i < 8; ++i)
        #pragma unroll
        for (int j = 0; j < 4; ++j) acc[i][j] = 0ull;

    // prologue stage kt=0
    {
        unsigned sb = smem_u32(w2s);
        #pragma unroll
        for (int q = 0; q < 4; ++q) {
            int f4 = tid + 256*q;
            cp_async16(sb + f4*16, w2 + f4*4);
        }
        cp_commit();
    }
    cp_wait0();
    __syncthreads();

    #pragma unroll 1
    for (int t = 0; t < 16; ++t) {
        if (t < 15) {
            unsigned sb = smem_u32(w2s + ((t+1)&1) * 4096);
            const float* gsrc = w2 + (size_t)(t+1)*KT*256;
            #pragma unroll
            for (int q = 0; q < 4; ++q) {
                int f4 = tid + 256*q;
                cp_async16(sb + f4*16, gsrc + f4*4);
            }
            cp_commit();
        }
        const float* wb = w2s + (t&1) * 4096;
        #pragma unroll
        for (int k = 0; k < KT; ++k) {
            const int kk = t*KT + k;
            ull a8[8];
            #pragma unroll
            for (int i = 0; i < 8; ++i)
                a8[i] = *(const ull*)&hdup[(r0+i)*512 + 2*kk];
            ulonglong2 bA = *(const ulonglong2*)&wb[k*256 + c0];
            ulonglong2 bB = *(const ulonglong2*)&wb[k*256 + c0 + 4];
            #pragma unroll
            for (int i = 0; i < 8; ++i) {
                ffma2(acc[i][0], a8[i], bA.x);
                ffma2(acc[i][1], a8[i], bA.y);
                ffma2(acc[i][2], a8[i], bB.x);
                ffma2(acc[i][3], a8[i], bB.y);
            }
        }
        cp_wait0();
        __syncthreads();
    }

    // ---- phase 3: features = E + b2 + Q; store + stage into smem (fs) ----
    float* fs = sm;  // reuse hdup region: 64 x 260
    #pragma unroll
    for (int i = 0; i < 8; ++i) {
        const int rl  = r0 + i;
        const int row = rowBase + rl;
        float e[8];
        #pragma unroll
        for (int j = 0; j < 4; ++j) {
            union { ull u; float2 f; } cv; cv.u = acc[i][j];
            e[2*j] = cv.f.x; e[2*j+1] = cv.f.y;
        }
        #pragma unroll
        for (int c = 0; c < 8; ++c) e[c] += b2s[c0 + c];
        if (row < N) {
            const float4 q0 = *(const float4*)&Q[(size_t)row*256 + c0];
            const float4 q1 = *(const float4*)&Q[(size_t)row*256 + c0 + 4];
            e[0]+=q0.x; e[1]+=q0.y; e[2]+=q0.z; e[3]+=q0.w;
            e[4]+=q1.x; e[5]+=q1.y; e[6]+=q1.z; e[7]+=q1.w;
            *(float4*)&out[(size_t)row*256 + c0]     = make_float4(e[0],e[1],e[2],e[3]);
            *(float4*)&out[(size_t)row*256 + c0 + 4] = make_float4(e[4],e[5],e[6],e[7]);
        }
        *(float4*)&fs[rl*260 + c0]     = make_float4(e[0],e[1],e[2],e[3]);
        *(float4*)&fs[rl*260 + c0 + 4] = make_float4(e[4],e[5],e[6],e[7]);
    }
    __syncthreads();

    // ---- phase 4: lf matmul (256->18), sigmoid, corners, refs ----
    {
        const int rl    = wrp * 8 + (lane >> 2);
        const int cpart = lane & 3;
        const int row   = rowBase + rl;
        float s[18];
        #pragma unroll
        for (int j = 0; j < 18; ++j) s[j] = 0.f;
        const int cbase = cpart * 64;
        #pragma unroll 1
        for (int u = 0; u < 64; u += 4) {
            float4 fv = *(const float4*)&fs[rl*260 + cbase + u];
            const float fvals[4] = {fv.x, fv.y, fv.z, fv.w};
            #pragma unroll
            for (int p = 0; p < 4; ++p) {
                const float f = fvals[p];
                const int c = cbase + u + p;
                const float4 l0 = *(const float4*)&lfws[c*20 + 0];
                const float4 l1 = *(const float4*)&lfws[c*20 + 4];
                const float4 l2 = *(const float4*)&lfws[c*20 + 8];
                const float4 l3 = *(const float4*)&lfws[c*20 + 12];
                const float2 l4 = *(const float2*)&lfws[c*20 + 16];
                s[0]  = fmaf(f, l0.x, s[0]);  s[1]  = fmaf(f, l0.y, s[1]);
                s[2]  = fmaf(f, l0.z, s[2]);  s[3]  = fmaf(f, l0.w, s[3]);
                s[4]  = fmaf(f, l1.x, s[4]);  s[5]  = fmaf(f, l1.y, s[5]);
                s[6]  = fmaf(f, l1.z, s[6]);  s[7]  = fmaf(f, l1.w, s[7]);
                s[8]  = fmaf(f, l2.x, s[8]);  s[9]  = fmaf(f, l2.y, s[9]);
                s[10] = fmaf(f, l2.z, s[10]); s[11] = fmaf(f, l2.w, s[11]);
                s[12] = fmaf(f, l3.x, s[12]); s[13] = fmaf(f, l3.y, s[13]);
                s[14] = fmaf(f, l3.z, s[14]); s[15] = fmaf(f, l3.w, s[15]);
                s[16] = fmaf(f, l4.x, s[16]); s[17] = fmaf(f, l4.y, s[17]);
            }
        }
        #pragma unroll
        for (int j = 0; j < 18; ++j) {
            s[j] += __shfl_xor_sync(0xffffffffu, s[j], 1);
            s[j] += __shfl_xor_sync(0xffffffffu, s[j], 2);
        }

        if (row < N) {
            const float mx = mu[row*3], my = mu[row*3+1], mz = mu[row*3+2];
            const float sx = sc[row*3]*0.5f, sy = sc[row*3+1]*0.5f, sz = sc[row*3+2]*0.5f;
            float qw = rot[row*4], qx = rot[row*4+1], qy = rot[row*4+2], qz = rot[row*4+3];
            const float nrm = fmaxf(sqrtf(qw*qw + qx*qx + qy*qy + qz*qz), 1e-8f);
            const float inr = 1.f / nrm;
            qw *= inr; qx *= inr; qy *= inr; qz *= inr;
            const float r00 = 1.f - 2.f*(qy*qy + qz*qz), r01 = 2.f*(qx*qy - qz*qw), r02 = 2.f*(qx*qz + qy*qw);
            const float r10 = 2.f*(qx*qy + qz*qw), r11 = 1.f - 2.f*(qx*qx + qz*qz), r12 = 2.f*(qy*qz - qx*qw);
            const float r20 = 2.f*(qx*qz - qy*qw), r21 = 2.f*(qy*qz + qx*qw), r22 = 1.f - 2.f*(qx*qx + qy*qy);

            const size_t OUT_CORN = (size_t)N * 256;
            const size_t OUT_XY   = OUT_CORN + (size_t)N * 33;
            const size_t OUT_XZ   = OUT_XY + (size_t)N * 22;
            const size_t OUT_YZ   = OUT_XZ + (size_t)N * 22;
            const float invxy = 1.f / (102.4f + 1e-6f);
            const float invz  = 1.f / (8.0f + 1e-6f);

            #pragma unroll
            for (int mm = 0; mm < 3; ++mm) {
                const int m = cpart + mm*4;
                if (m < 11) {
                    float lx, ly, lz;
                    if (m == 0)      { lx = 0.f;  ly = 0.f;  lz = 0.f; }
                    else if (m == 1) { lx = 0.f;  ly = sy;   lz = 0.f; }
                    else if (m == 2) { lx = 0.f;  ly = -sy;  lz = 0.f; }
                    else if (m == 3) { lx = sx;   ly = 0.f;  lz = 0.f; }
                    else if (m == 4) { lx = -sx;  ly = 0.f;  lz = 0.f; }
                    else {
                        const int j = (m - 5) * 3;
                        const float t0 = s[j]   + lfbs[j];
                        const float t1 = s[j+1] + lfbs[j+1];
                        const float t2 = s[j+2] + lfbs[j+2];
                        const float g0 = 1.f / (1.f + __expf(-t0));
                        const float g1 = 1.f / (1.f + __expf(-t1));
                        const float g2 = 1.f / (1.f + __expf(-t2));
                        lx = (g0 - 0.5f) * sx;
                        ly = (g1 - 0.5f) * sy;
                        lz = (g2 - 0.5f) * sz;
                    }
                    const float cxv = r00*lx + r01*ly + r02*lz + mx;
                    const float cyv = r10*lx + r11*ly + r12*lz + my;
                    const float czv = r20*lx + r21*ly + r22*lz + mz;
                    const size_t cb = OUT_CORN + ((size_t)row*11 + m)*3;
                    out[cb]   = cxv;
                    out[cb+1] = cyv;
                    out[cb+2] = czv;
                    const float nx = fminf(fmaxf((cxv + 51.2f) * invxy, 0.f), 1.f);
                    const float ny = fminf(fmaxf((cyv + 51.2f) * invxy, 0.f), 1.f);
                    const float nz = fminf(fmaxf((czv + 5.0f)  * invz,  0.f), 1.f);
                    const size_t rb = (size_t)row*11 + m;
                    out[OUT_XY + rb*2]     = nx;
                    out[OUT_XY + rb*2 + 1] = ny;
                    out[OUT_XZ + rb*2]     = nx;
                    out[OUT_XZ + rb*2 + 1] = nz;
                    out[OUT_YZ + rb*2]     = ny;
                    out[OUT_YZ + rb*2 + 1] = nz;
                }
            }
        }
    }
}

extern "C" void kernel_launch(void* const* d_in, const int* in_sizes, int n_in,
                              void* d_out, int out_size) {
    const float* mu    = (const float*)d_in[0];
    const float* sc    = (const float*)d_in[1];
    const float* rot   = (const float*)d_in[2];
    const float* Q     = (const float*)d_in[3];
    const float* w1    = (const float*)d_in[4];
    const float* b1    = (const float*)d_in[5];
    const float* gamma = (const float*)d_in[6];
    const float* beta  = (const float*)d_in[7];
    const float* w2    = (const float*)d_in[8];
    const float* b2    = (const float*)d_in[9];
    const float* lfw   = (const float*)d_in[10];
    const float* lfb   = (const float*)d_in[11];
    float* out = (float*)d_out;
    const int N = in_sizes[0] / 3;

    const int smem_bytes = SMEM_FLOATS * sizeof(float);
    cudaFuncSetAttribute(gauss_fused_kernel,
                         cudaFuncAttributeMaxDynamicSharedMemorySize, smem_bytes);
    const int blocks = (N + MT - 1) / MT;
    gauss_fused_kernel<<<blocks, 256, smem_bytes>>>(
        mu, sc, rot, Q, w1, b1, gamma, beta, w2, b2, lfw, lfb, out, N);
}

// round 3
// speedup vs baseline: 1.1311x; 1.1311x over previous
#include <cuda_runtime.h>
#include <cuda_bf16.h>
#include <mma.h>
#include <cstdint>

using namespace nvcuda;
typedef unsigned int u32;

#define MT 64
#define LDH 264            // bf16 elements per hs row (528B stride, conflict-free ldmatrix)
#define LDF 264            // fp32 elements per fs row

// smem float offsets
#define HS_F   0           // 16896 floats: hs_hi bf16[64*264] then hs_lo ; doubles as fs fp32[64*264]
#define B_F    16896       // 16896 floats: 2 bufs x (hi bf16[32*264] + lo bf16[32*264])
#define W1S_F  33792
#define B1S_F  36352
#define GMS_F  36608
#define BTS_F  36864
#define B2S_F  37120
#define LFW_F  37376       // 256 x 20
#define LFB_F  42496
#define SMEM_FLOATS 42528

__device__ __nv_bfloat16 g_w2hi[65536];   // [K=256][N=256]
__device__ __nv_bfloat16 g_w2lo[65536];

__device__ __forceinline__ u32 smem_u32(const void* p) {
    return (u32)__cvta_generic_to_shared(p);
}
__device__ __forceinline__ void cp_async16(u32 s, const void* g) {
    asm volatile("cp.async.cg.shared.global [%0], [%1], 16;" :: "r"(s), "l"(g));
}
__device__ __forceinline__ void cp_commit() { asm volatile("cp.async.commit_group;"); }
template<int NN> __device__ __forceinline__ void cp_wait() {
    asm volatile("cp.async.wait_group %0;" :: "n"(NN) : "memory");
}

__global__ void w2_convert_kernel(const float* __restrict__ w2) {
    const int k = blockIdx.x, n = threadIdx.x;
    const float x = w2[k * 256 + n];
    const __nv_bfloat16 h = __float2bfloat16(x);
    g_w2hi[k * 256 + n] = h;
    g_w2lo[k * 256 + n] = __float2bfloat16(x - __bfloat162float(h));
}

// stage B chunk (32 k-rows of w2 hi+lo) into buffer buf
__device__ __forceinline__ void load_chunk(u32 smb, int buf, int kt, int tid) {
    const u32 base = smb + (B_F + buf * 8448) * 4;
    #pragma unroll
    for (int q = 0; q < 8; ++q) {
        const int idx = tid + 256 * q;            // 0..2047
        const int hm  = idx >> 10;                // 0=hi, 1=lo
        const int i   = idx & 1023;
        const int r   = i >> 5;                   // k-row 0..31
        const int j   = i & 31;                   // col chunk (8 bf16)
        const u32 dst = base + hm * (4224 * 4) + r * 528 + j * 16;
        const __nv_bfloat16* src = (hm ? g_w2lo : g_w2hi) + (kt + r) * 256 + j * 8;
        cp_async16(dst, src);
    }
}

__global__ void __launch_bounds__(256, 1)
gauss_wmma_kernel(const float* __restrict__ mu, const float* __restrict__ sc,
                  const float* __restrict__ rot, const float* __restrict__ Q,
                  const float* __restrict__ w1, const float* __restrict__ b1,
                  const float* __restrict__ gamma, const float* __restrict__ beta,
                  const float* __restrict__ b2,
                  const float* __restrict__ lfw, const float* __restrict__ lfb,
                  float* __restrict__ out, int N)
{
    extern __shared__ float sm[];
    const u32 smb = smem_u32(sm);
    __nv_bfloat16* hs_hi = (__nv_bfloat16*)(sm + HS_F);
    __nv_bfloat16* hs_lo = hs_hi + 64 * LDH;
    float* fs   = sm + HS_F;
    float* w1s  = sm + W1S_F;
    float* b1s  = sm + B1S_F;
    float* gms  = sm + GMS_F;
    float* bts  = sm + BTS_F;
    float* b2s  = sm + B2S_F;
    float* lfws = sm + LFW_F;
    float* lfbs = sm + LFB_F;

    const int tid  = threadIdx.x;
    const int lane = tid & 31;
    const int wid  = tid >> 5;
    const int rowBase = blockIdx.x * MT;

    // kick off B prefetch for chunks 0 and 1 (independent of phase 1)
    load_chunk(smb, 0, 0, tid);  cp_commit();
    load_chunk(smb, 1, 32, tid); cp_commit();

    // stage constants
    #pragma unroll
    for (int i = tid; i < 2560; i += 256) w1s[i] = w1[i];
    b1s[tid] = b1[tid]; gms[tid] = gamma[tid]; bts[tid] = beta[tid]; b2s[tid] = b2[tid];
    {
        const int c = tid;
        #pragma unroll
        for (int j = 0; j < 18; ++j) lfws[c*20 + j] = lfw[c*18 + j];
        lfws[c*20 + 18] = 0.f; lfws[c*20 + 19] = 0.f;
    }
    if (tid < 18) lfbs[tid] = lfb[tid];
    __syncthreads();

    // ---- phase 1: h = relu(LN(geo@w1+b1)) -> hs (bf16 hi/lo) ----
    #pragma unroll 1
    for (int ii = 0; ii < 8; ++ii) {
        const int rl  = wid * 8 + ii;
        const int row = rowBase + rl;
        const bool valid = (row < N);
        float g[10];
        if (valid) {
            g[0]=mu[row*3]; g[1]=mu[row*3+1]; g[2]=mu[row*3+2];
            g[3]=sc[row*3]; g[4]=sc[row*3+1]; g[5]=sc[row*3+2];
            g[6]=rot[row*4]; g[7]=rot[row*4+1]; g[8]=rot[row*4+2]; g[9]=rot[row*4+3];
        } else {
            #pragma unroll
            for (int i = 0; i < 10; ++i) g[i] = 0.f;
        }
        float hv[8]; float s = 0.f;
        #pragma unroll
        for (int jj = 0; jj < 8; ++jj) {
            const int d = lane + 32 * jj;
            float a = b1s[d];
            #pragma unroll
            for (int i = 0; i < 10; ++i) a = fmaf(g[i], w1s[i*256 + d], a);
            hv[jj] = a; s += a;
        }
        #pragma unroll
        for (int o = 16; o; o >>= 1) s += __shfl_xor_sync(0xffffffffu, s, o);
        const float mean = s * (1.f/256.f);
        float v = 0.f;
        #pragma unroll
        for (int jj = 0; jj < 8; ++jj) { float t = hv[jj] - mean; v = fmaf(t, t, v); }
        #pragma unroll
        for (int o = 16; o; o >>= 1) v += __shfl_xor_sync(0xffffffffu, v, o);
        const float inv = rsqrtf(v * (1.f/256.f) + 1e-5f);
        #pragma unroll
        for (int jj = 0; jj < 8; ++jj) {
            const int d = lane + 32 * jj;
            float t = (hv[jj] - mean) * inv * gms[d] + bts[d];
            t = fmaxf(t, 0.f);
            if (!valid) t = 0.f;
            const __nv_bfloat16 th = __float2bfloat16(t);
            hs_hi[rl * LDH + d] = th;
            hs_lo[rl * LDH + d] = __float2bfloat16(t - __bfloat162float(th));
        }
    }
    __syncthreads();

    // ---- phase 2: E = h @ w2 via bf16 hi/lo wmma ----
    const int wm = wid & 1;        // 2 warps along M (32 rows each)
    const int wn = wid >> 1;       // 4 warps along N (64 cols each)

    wmma::fragment<wmma::accumulator, 16,16,16, float> acc[2][4];
    #pragma unroll
    for (int mi = 0; mi < 2; ++mi)
        #pragma unroll
        for (int ni = 0; ni < 4; ++ni) wmma::fill_fragment(acc[mi][ni], 0.f);

    cp_wait<1>(); __syncthreads();   // chunk 0 ready

    #pragma unroll 1
    for (int t = 0; t < 8; ++t) {
        const int buf = t & 1;
        const __nv_bfloat16* bhi = (const __nv_bfloat16*)(sm + B_F + buf * 8448);
        const __nv_bfloat16* blo = bhi + 32 * LDH;

        #pragma unroll
        for (int s = 0; s < 2; ++s) {
            const int kk = t * 32 + s * 16;   // global k
            const int ks = s * 16;            // k within buffer
            wmma::fragment<wmma::matrix_a, 16,16,16, __nv_bfloat16, wmma::row_major> a_hi[2], a_lo[2];
            wmma::fragment<wmma::matrix_b, 16,16,16, __nv_bfloat16, wmma::row_major> b_hi[4], b_lo[4];
            #pragma unroll
            for (int mi = 0; mi < 2; ++mi) {
                wmma::load_matrix_sync(a_hi[mi], hs_hi + (wm*32 + mi*16) * LDH + kk, LDH);
                wmma::load_matrix_sync(a_lo[mi], hs_lo + (wm*32 + mi*16) * LDH + kk, LDH);
            }
            #pragma unroll
            for (int ni = 0; ni < 4; ++ni) {
                wmma::load_matrix_sync(b_hi[ni], bhi + ks * LDH + wn*64 + ni*16, LDH);
                wmma::load_matrix_sync(b_lo[ni], blo + ks * LDH + wn*64 + ni*16, LDH);
            }
            #pragma unroll
            for (int mi = 0; mi < 2; ++mi)
                #pragma unroll
                for (int ni = 0; ni < 4; ++ni) {
                    wmma::mma_sync(acc[mi][ni], a_hi[mi], b_hi[ni], acc[mi][ni]);
                    wmma::mma_sync(acc[mi][ni], a_hi[mi], b_lo[ni], acc[mi][ni]);
                    wmma::mma_sync(acc[mi][ni], a_lo[mi], b_hi[ni], acc[mi][ni]);
                }
        }
        __syncthreads();   // done reading buf
        if (t + 2 < 8) { load_chunk(smb, buf, (t + 2) * 32, tid); cp_commit(); }
        if (t + 1 < 8) {
            if (t + 2 < 8) { cp_wait<1>(); } else { cp_wait<0>(); }
            __syncthreads();
        }
    }
    __syncthreads();   // hs dead; fs takes over the region

    // ---- phase 3a: acc -> fs ----
    #pragma unroll
    for (int mi = 0; mi < 2; ++mi)
        #pragma unroll
        for (int ni = 0; ni < 4; ++ni)
            wmma::store_matrix_sync(fs + (wm*32 + mi*16) * LDF + wn*64 + ni*16,
                                    acc[mi][ni], LDF, wmma::mem_row_major);
    __syncthreads();

    // ---- phase 3b: features = E + b2 + Q; coalesced write; fs updated ----
    #pragma unroll 4
    for (int r = 0; r < MT; ++r) {
        const int row = rowBase + r;
        float v = fs[r * LDF + tid] + b2s[tid];
        if (row < N) {
            v += Q[(size_t)row * 256 + tid];
            out[(size_t)row * 256 + tid] = v;
        }
        fs[r * LDF + tid] = v;
    }
    __syncthreads();

    // ---- phase 4: lf matmul (256->18), sigmoid, corners, refs ----
    {
        const int rl    = wid * 8 + (lane >> 2);
        const int cpart = lane & 3;
        const int row   = rowBase + rl;
        float s[18];
        #pragma unroll
        for (int j = 0; j < 18; ++j) s[j] = 0.f;
        const int cbase = cpart * 64;
        #pragma unroll 1
        for (int u = 0; u < 64; u += 4) {
            float4 fv = *(const float4*)&fs[rl * LDF + cbase + u];
            const float fvals[4] = {fv.x, fv.y, fv.z, fv.w};
            #pragma unroll
            for (int p = 0; p < 4; ++p) {
                const float f = fvals[p];
                const int c = cbase + u + p;
                const float4 l0 = *(const float4*)&lfws[c*20 + 0];
                const float4 l1 = *(const float4*)&lfws[c*20 + 4];
                const float4 l2 = *(const float4*)&lfws[c*20 + 8];
                const float4 l3 = *(const float4*)&lfws[c*20 + 12];
                const float2 l4 = *(const float2*)&lfws[c*20 + 16];
                s[0]  = fmaf(f, l0.x, s[0]);  s[1]  = fmaf(f, l0.y, s[1]);
                s[2]  = fmaf(f, l0.z, s[2]);  s[3]  = fmaf(f, l0.w, s[3]);
                s[4]  = fmaf(f, l1.x, s[4]);  s[5]  = fmaf(f, l1.y, s[5]);
                s[6]  = fmaf(f, l1.z, s[6]);  s[7]  = fmaf(f, l1.w, s[7]);
                s[8]  = fmaf(f, l2.x, s[8]);  s[9]  = fmaf(f, l2.y, s[9]);
                s[10] = fmaf(f, l2.z, s[10]); s[11] = fmaf(f, l2.w, s[11]);
                s[12] = fmaf(f, l3.x, s[12]); s[13] = fmaf(f, l3.y, s[13]);
                s[14] = fmaf(f, l3.z, s[14]); s[15] = fmaf(f, l3.w, s[15]);
                s[16] = fmaf(f, l4.x, s[16]); s[17] = fmaf(f, l4.y, s[17]);
            }
        }
        #pragma unroll
        for (int j = 0; j < 18; ++j) {
            s[j] += __shfl_xor_sync(0xffffffffu, s[j], 1);
            s[j] += __shfl_xor_sync(0xffffffffu, s[j], 2);
        }

        if (row < N) {
            const float mx = mu[row*3], my = mu[row*3+1], mz = mu[row*3+2];
            const float sx = sc[row*3]*0.5f, sy = sc[row*3+1]*0.5f, sz = sc[row*3+2]*0.5f;
            float qw = rot[row*4], qx = rot[row*4+1], qy = rot[row*4+2], qz = rot[row*4+3];
            const float nrm = fmaxf(sqrtf(qw*qw + qx*qx + qy*qy + qz*qz), 1e-8f);
            const float inr = 1.f / nrm;
            qw *= inr; qx *= inr; qy *= inr; qz *= inr;
            const float r00 = 1.f - 2.f*(qy*qy + qz*qz), r01 = 2.f*(qx*qy - qz*qw), r02 = 2.f*(qx*qz + qy*qw);
            const float r10 = 2.f*(qx*qy + qz*qw), r11 = 1.f - 2.f*(qx*qx + qz*qz), r12 = 2.f*(qy*qz - qx*qw);
            const float r20 = 2.f*(qx*qz - qy*qw), r21 = 2.f*(qy*qz + qx*qw), r22 = 1.f - 2.f*(qx*qx + qy*qy);

            const size_t OUT_CORN = (size_t)N * 256;
            const size_t OUT_XY   = OUT_CORN + (size_t)N * 33;
            const size_t OUT_XZ   = OUT_XY + (size_t)N * 22;
            const size_t OUT_YZ   = OUT_XZ + (size_t)N * 22;
            const float invxy = 1.f / (102.4f + 1e-6f);
            const float invz  = 1.f / (8.0f + 1e-6f);

            #pragma unroll
            for (int mm = 0; mm < 3; ++mm) {
                const int m = cpart + mm * 4;
                if (m < 11) {
                    float lx, ly, lz;
                    if (m == 0)      { lx = 0.f;  ly = 0.f;  lz = 0.f; }
                    else if (m == 1) { lx = 0.f;  ly = sy;   lz = 0.f; }
                    else if (m == 2) { lx = 0.f;  ly = -sy;  lz = 0.f; }
                    else if (m == 3) { lx = sx;   ly = 0.f;  lz = 0.f; }
                    else if (m == 4) { lx = -sx;  ly = 0.f;  lz = 0.f; }
                    else {
                        const int j = (m - 5) * 3;
                        const float t0 = s[j]   + lfbs[j];
                        const float t1 = s[j+1] + lfbs[j+1];
                        const float t2 = s[j+2] + lfbs[j+2];
                        const float g0 = 1.f / (1.f + __expf(-t0));
                        const float g1 = 1.f / (1.f + __expf(-t1));
                        const float g2 = 1.f / (1.f + __expf(-t2));
                        lx = (g0 - 0.5f) * sx;
                        ly = (g1 - 0.5f) * sy;
                        lz = (g2 - 0.5f) * sz;
                    }
                    const float cxv = r00*lx + r01*ly + r02*lz + mx;
                    const float cyv = r10*lx + r11*ly + r12*lz + my;
                    const float czv = r20*lx + r21*ly + r22*lz + mz;
                    const size_t cb = OUT_CORN + ((size_t)row * 11 + m) * 3;
                    out[cb]   = cxv;
                    out[cb+1] = cyv;
                    out[cb+2] = czv;
                    const float nx = fminf(fmaxf((cxv + 51.2f) * invxy, 0.f), 1.f);
                    const float ny = fminf(fmaxf((cyv + 51.2f) * invxy, 0.f), 1.f);
                    const float nz = fminf(fmaxf((czv + 5.0f)  * invz,  0.f), 1.f);
                    const size_t rb = (size_t)row * 11 + m;
                    out[OUT_XY + rb*2]     = nx;
                    out[OUT_XY + rb*2 + 1] = ny;
                    out[OUT_XZ + rb*2]     = nx;
                    out[OUT_XZ + rb*2 + 1] = nz;
                    out[OUT_YZ + rb*2]     = ny;
                    out[OUT_YZ + rb*2 + 1] = nz;
                }
            }
        }
    }
}

extern "C" void kernel_launch(void* const* d_in, const int* in_sizes, int n_in,
                              void* d_out, int out_size) {
    const float* mu    = (const float*)d_in[0];
    const float* sc    = (const float*)d_in[1];
    const float* rot   = (const float*)d_in[2];
    const float* Q     = (const float*)d_in[3];
    const float* w1    = (const float*)d_in[4];
    const float* b1    = (const float*)d_in[5];
    const float* gamma = (const float*)d_in[6];
    const float* beta  = (const float*)d_in[7];
    const float* w2    = (const float*)d_in[8];
    const float* b2    = (const float*)d_in[9];
    const float* lfw   = (const float*)d_in[10];
    const float* lfb   = (const float*)d_in[11];
    float* out = (float*)d_out;
    const int N = in_sizes[0] / 3;

    w2_convert_kernel<<<256, 256>>>(w2);

    const int smem_bytes = SMEM_FLOATS * sizeof(float);
    cudaFuncSetAttribute(gauss_wmma_kernel,
                         cudaFuncAttributeMaxDynamicSharedMemorySize, smem_bytes);
    const int blocks = (N + MT - 1) / MT;
    gauss_wmma_kernel<<<blocks, 256, smem_bytes>>>(
        mu, sc, rot, Q, w1, b1, gamma, beta, b2, lfw, lfb, out, N);
}

// round 4
// speedup vs baseline: 1.4400x; 1.2730x over previous
#include <cuda_runtime.h>
#include <cuda_bf16.h>
#include <mma.h>
#include <cstdint>

using namespace nvcuda;
typedef unsigned int u32;

#define MT 64
#define LDH 264            // bf16 per hs row (528B stride; multiple of 8 for wmma)
#define LDF 264            // fp32 per fs row (kernel A)
#define LDFB 260           // fp32 per fs row (kernel B)

// ---------------- kernel A smem (floats) ----------------
// hs: hi bf16[64*264] + lo bf16[64*264]  = 16896 floats (doubles as fs fp32[64*264])
// B : 2 bufs x (hi 16x264 + lo 16x264) bf16 = 8448 floats
// w1s 2560 | b1s 256 | gms 256 | bts 256
#define HS_F   0
#define B_F    16896
#define W1S_F  25344
#define B1S_F  27904
#define GMS_F  28160
#define BTS_F  28416
#define SMEM_A_FLOATS 28672          // 114688 B  (2 CTAs/SM: <=115712)

// ---------------- kernel B smem (floats) ----------------
#define FSB_F  0                     // 64 x 260
#define LFW_F  16640                 // 256 x 20
#define LFB_F  21760
#define SMEM_B_FLOATS 21792          // 87168 B (2 CTAs/SM)

__device__ __nv_bfloat16 g_w2hi[65536];   // [K=256][N=256]
__device__ __nv_bfloat16 g_w2lo[65536];

__device__ __forceinline__ u32 smem_u32(const void* p) {
    return (u32)__cvta_generic_to_shared(p);
}
__device__ __forceinline__ void cp_async16(u32 s, const void* g) {
    asm volatile("cp.async.cg.shared.global [%0], [%1], 16;" :: "r"(s), "l"(g));
}
__device__ __forceinline__ void cp_commit() { asm volatile("cp.async.commit_group;"); }
template<int NN> __device__ __forceinline__ void cp_wait() {
    asm volatile("cp.async.wait_group %0;" :: "n"(NN) : "memory");
}

__global__ void w2_convert_kernel(const float* __restrict__ w2) {
    const int k = blockIdx.x, n = threadIdx.x;
    const float x = w2[k * 256 + n];
    const __nv_bfloat16 h = __float2bfloat16(x);
    g_w2hi[k * 256 + n] = h;
    g_w2lo[k * 256 + n] = __float2bfloat16(x - __bfloat162float(h));
}

// stage a 16-k-row chunk of w2 (hi+lo) into buffer buf
__device__ __forceinline__ void load_chunk(u32 smb, int buf, int kt, int tid) {
    const u32 base = smb + B_F * 4 + buf * 16896;
    #pragma unroll
    for (int q = 0; q < 4; ++q) {
        const int idx = tid + 256 * q;          // 0..1023
        const int hm  = idx >> 9;               // 0=hi, 1=lo
        const int i   = idx & 511;
        const int r   = i >> 5;                 // k-row 0..15
        const int j   = i & 31;                 // 8-bf16 chunk
        const u32 dst = base + hm * 8448 + r * 528 + j * 16;
        const __nv_bfloat16* src = (hm ? g_w2lo : g_w2hi) + (kt + r) * 256 + j * 8;
        cp_async16(dst, src);
    }
}

// =================== Kernel A: LN + GEMM + features ===================
__global__ void __launch_bounds__(256, 2)
gauss_gemm_kernel(const float* __restrict__ mu, const float* __restrict__ sc,
                  const float* __restrict__ rot, const float* __restrict__ Q,
                  const float* __restrict__ w1, const float* __restrict__ b1,
                  const float* __restrict__ gamma, const float* __restrict__ beta,
                  const float* __restrict__ b2,
                  float* __restrict__ out, int N)
{
    extern __shared__ float sm[];
    const u32 smb = smem_u32(sm);
    __nv_bfloat16* hs_hi = (__nv_bfloat16*)(sm + HS_F);
    __nv_bfloat16* hs_lo = hs_hi + 64 * LDH;
    float* fs   = sm + HS_F;
    float* w1s  = sm + W1S_F;
    float* b1s  = sm + B1S_F;
    float* gms  = sm + GMS_F;
    float* bts  = sm + BTS_F;

    const int tid  = threadIdx.x;
    const int lane = tid & 31;
    const int wid  = tid >> 5;
    const int rowBase = blockIdx.x * MT;

    // prefetch first two B chunks
    load_chunk(smb, 0, 0, tid);  cp_commit();
    load_chunk(smb, 1, 16, tid); cp_commit();

    // stage constants
    #pragma unroll
    for (int i = tid; i < 2560; i += 256) w1s[i] = w1[i];
    b1s[tid] = b1[tid]; gms[tid] = gamma[tid]; bts[tid] = beta[tid];
    __syncthreads();

    // ---- phase 1: h = relu(LN(geo@w1+b1)) -> hs bf16 hi/lo ----
    #pragma unroll 1
    for (int ii = 0; ii < 8; ++ii) {
        const int rl  = wid * 8 + ii;
        const int row = rowBase + rl;
        const bool valid = (row < N);
        float g[10];
        if (valid) {
            g[0]=mu[row*3]; g[1]=mu[row*3+1]; g[2]=mu[row*3+2];
            g[3]=sc[row*3]; g[4]=sc[row*3+1]; g[5]=sc[row*3+2];
            g[6]=rot[row*4]; g[7]=rot[row*4+1]; g[8]=rot[row*4+2]; g[9]=rot[row*4+3];
        } else {
            #pragma unroll
            for (int i = 0; i < 10; ++i) g[i] = 0.f;
        }
        float hv[8]; float s = 0.f;
        #pragma unroll
        for (int jj = 0; jj < 8; ++jj) {
            const int d = lane + 32 * jj;
            float a = b1s[d];
            #pragma unroll
            for (int i = 0; i < 10; ++i) a = fmaf(g[i], w1s[i*256 + d], a);
            hv[jj] = a; s += a;
        }
        #pragma unroll
        for (int o = 16; o; o >>= 1) s += __shfl_xor_sync(0xffffffffu, s, o);
        const float mean = s * (1.f/256.f);
        float v = 0.f;
        #pragma unroll
        for (int jj = 0; jj < 8; ++jj) { float t = hv[jj] - mean; v = fmaf(t, t, v); }
        #pragma unroll
        for (int o = 16; o; o >>= 1) v += __shfl_xor_sync(0xffffffffu, v, o);
        const float inv = rsqrtf(v * (1.f/256.f) + 1e-5f);
        #pragma unroll
        for (int jj = 0; jj < 8; ++jj) {
            const int d = lane + 32 * jj;
            float t = (hv[jj] - mean) * inv * gms[d] + bts[d];
            t = fmaxf(t, 0.f);
            if (!valid) t = 0.f;
            const __nv_bfloat16 th = __float2bfloat16(t);
            hs_hi[rl * LDH + d] = th;
            hs_lo[rl * LDH + d] = __float2bfloat16(t - __bfloat162float(th));
        }
    }
    __syncthreads();

    // ---- phase 2: E = h @ w2 via bf16 hi/lo wmma (16 chunks of k=16) ----
    const int wm = wid & 1;        // 2 warps along M (32 rows each)
    const int wn = wid >> 1;       // 4 warps along N (64 cols each)

    wmma::fragment<wmma::accumulator, 16,16,16, float> acc[2][4];
    #pragma unroll
    for (int mi = 0; mi < 2; ++mi)
        #pragma unroll
        for (int ni = 0; ni < 4; ++ni) wmma::fill_fragment(acc[mi][ni], 0.f);

    #pragma unroll 1
    for (int t = 0; t < 16; ++t) {
        if (t < 15) { cp_wait<1>(); } else { cp_wait<0>(); }
        __syncthreads();

        const int buf = t & 1;
        const __nv_bfloat16* bhi = (const __nv_bfloat16*)(sm + B_F) + buf * 8448;
        const __nv_bfloat16* blo = bhi + 16 * LDH;
        const int kk = t * 16;

        wmma::fragment<wmma::matrix_a, 16,16,16, __nv_bfloat16, wmma::row_major> a_hi[2], a_lo[2];
        #pragma unroll
        for (int mi = 0; mi < 2; ++mi) {
            wmma::load_matrix_sync(a_hi[mi], hs_hi + (wm*32 + mi*16) * LDH + kk, LDH);
            wmma::load_matrix_sync(a_lo[mi], hs_lo + (wm*32 + mi*16) * LDH + kk, LDH);
        }
        #pragma unroll
        for (int ni = 0; ni < 4; ++ni) {
            wmma::fragment<wmma::matrix_b, 16,16,16, __nv_bfloat16, wmma::row_major> b_hi, b_lo;
            wmma::load_matrix_sync(b_hi, bhi + wn*64 + ni*16, LDH);
            wmma::load_matrix_sync(b_lo, blo + wn*64 + ni*16, LDH);
            #pragma unroll
            for (int mi = 0; mi < 2; ++mi) {
                wmma::mma_sync(acc[mi][ni], a_hi[mi], b_hi, acc[mi][ni]);
                wmma::mma_sync(acc[mi][ni], a_hi[mi], b_lo, acc[mi][ni]);
                wmma::mma_sync(acc[mi][ni], a_lo[mi], b_hi, acc[mi][ni]);
            }
        }
        __syncthreads();
        if (t + 2 < 16) { load_chunk(smb, buf, (t + 2) * 16, tid); cp_commit(); }
    }
    __syncthreads();   // hs dead; fs takes over region

    // ---- phase 3a: acc -> fs ----
    #pragma unroll
    for (int mi = 0; mi < 2; ++mi)
        #pragma unroll
        for (int ni = 0; ni < 4; ++ni)
            wmma::store_matrix_sync(fs + (wm*32 + mi*16) * LDF + wn*64 + ni*16,
                                    acc[mi][ni], LDF, wmma::mem_row_major);
    __syncthreads();

    // ---- phase 3b: features = E + b2 + Q (batched MLP=8) ----
    const float b2v = __ldg(&b2[tid]);
    #pragma unroll 1
    for (int rb = 0; rb < MT; rb += 8) {
        float qv[8];
        #pragma unroll
        for (int k = 0; k < 8; ++k) {
            const int row = rowBase + rb + k;
            qv[k] = (row < N) ? Q[(size_t)row * 256 + tid] : 0.f;
        }
        #pragma unroll
        for (int k = 0; k < 8; ++k) {
            const int row = rowBase + rb + k;
            if (row < N)
                out[(size_t)row * 256 + tid] = fs[(rb + k) * LDF + tid] + b2v + qv[k];
        }
    }
}

// =================== Kernel B: lf matmul + corners + refs ===================
__global__ void __launch_bounds__(256, 2)
gauss_corner_kernel(const float* __restrict__ mu, const float* __restrict__ sc,
                    const float* __restrict__ rot,
                    const float* __restrict__ lfw, const float* __restrict__ lfb,
                    float* __restrict__ out, int N)
{
    extern __shared__ float sm[];
    float* fs   = sm + FSB_F;     // 64 x 260
    float* lfws = sm + LFW_F;     // 256 x 20
    float* lfbs = sm + LFB_F;

    const int tid  = threadIdx.x;
    const int lane = tid & 31;
    const int wid  = tid >> 5;
    const int rowBase = blockIdx.x * MT;

    {
        const int c = tid;
        #pragma unroll
        for (int j = 0; j < 18; ++j) lfws[c*20 + j] = lfw[c*18 + j];
        lfws[c*20 + 18] = 0.f; lfws[c*20 + 19] = 0.f;
    }
    if (tid < 18) lfbs[tid] = lfb[tid];

    // stage feature tile (batched MLP=8)
    #pragma unroll 1
    for (int rb = 0; rb < MT; rb += 8) {
        float fv[8];
        #pragma unroll
        for (int k = 0; k < 8; ++k) {
            const int row = rowBase + rb + k;
            fv[k] = (row < N) ? out[(size_t)row * 256 + tid] : 0.f;
        }
        #pragma unroll
        for (int k = 0; k < 8; ++k)
            fs[(rb + k) * LDFB + tid] = fv[k];
    }
    __syncthreads();

    // phase 4 (R1-proven): warp = 8 rows x 4 col-partitions
    const int rl    = wid * 8 + (lane >> 2);
    const int cpart = lane & 3;
    const int row   = rowBase + rl;
    float s[18];
    #pragma unroll
    for (int j = 0; j < 18; ++j) s[j] = 0.f;
    const int cbase = cpart * 64;
    #pragma unroll 1
    for (int u = 0; u < 64; u += 4) {
        float4 fv = *(const float4*)&fs[rl * LDFB + cbase + u];
        const float fvals[4] = {fv.x, fv.y, fv.z, fv.w};
        #pragma unroll
        for (int p = 0; p < 4; ++p) {
            const float f = fvals[p];
            const int c = cbase + u + p;
            const float4 l0 = *(const float4*)&lfws[c*20 + 0];
            const float4 l1 = *(const float4*)&lfws[c*20 + 4];
            const float4 l2 = *(const float4*)&lfws[c*20 + 8];
            const float4 l3 = *(const float4*)&lfws[c*20 + 12];
            const float2 l4 = *(const float2*)&lfws[c*20 + 16];
            s[0]  = fmaf(f, l0.x, s[0]);  s[1]  = fmaf(f, l0.y, s[1]);
            s[2]  = fmaf(f, l0.z, s[2]);  s[3]  = fmaf(f, l0.w, s[3]);
            s[4]  = fmaf(f, l1.x, s[4]);  s[5]  = fmaf(f, l1.y, s[5]);
            s[6]  = fmaf(f, l1.z, s[6]);  s[7]  = fmaf(f, l1.w, s[7]);
            s[8]  = fmaf(f, l2.x, s[8]);  s[9]  = fmaf(f, l2.y, s[9]);
            s[10] = fmaf(f, l2.z, s[10]); s[11] = fmaf(f, l2.w, s[11]);
            s[12] = fmaf(f, l3.x, s[12]); s[13] = fmaf(f, l3.y, s[13]);
            s[14] = fmaf(f, l3.z, s[14]); s[15] = fmaf(f, l3.w, s[15]);
            s[16] = fmaf(f, l4.x, s[16]); s[17] = fmaf(f, l4.y, s[17]);
        }
    }
    #pragma unroll
    for (int j = 0; j < 18; ++j) {
        s[j] += __shfl_xor_sync(0xffffffffu, s[j], 1);
        s[j] += __shfl_xor_sync(0xffffffffu, s[j], 2);
    }

    if (row < N) {
        const float mx = mu[row*3], my = mu[row*3+1], mz = mu[row*3+2];
        const float sx = sc[row*3]*0.5f, sy = sc[row*3+1]*0.5f, sz = sc[row*3+2]*0.5f;
        float qw = rot[row*4], qx = rot[row*4+1], qy = rot[row*4+2], qz = rot[row*4+3];
        const float nrm = fmaxf(sqrtf(qw*qw + qx*qx + qy*qy + qz*qz), 1e-8f);
        const float inr = 1.f / nrm;
        qw *= inr; qx *= inr; qy *= inr; qz *= inr;
        const float r00 = 1.f - 2.f*(qy*qy + qz*qz), r01 = 2.f*(qx*qy - qz*qw), r02 = 2.f*(qx*qz + qy*qw);
        const float r10 = 2.f*(qx*qy + qz*qw), r11 = 1.f - 2.f*(qx*qx + qz*qz), r12 = 2.f*(qy*qz - qx*qw);
        const float r20 = 2.f*(qx*qz - qy*qw), r21 = 2.f*(qy*qz + qx*qw), r22 = 1.f - 2.f*(qx*qx + qy*qy);

        const size_t OUT_CORN = (size_t)N * 256;
        const size_t OUT_XY   = OUT_CORN + (size_t)N * 33;
        const size_t OUT_XZ   = OUT_XY + (size_t)N * 22;
        const size_t OUT_YZ   = OUT_XZ + (size_t)N * 22;
        const float invxy = 1.f / (102.4f + 1e-6f);
        const float invz  = 1.f / (8.0f + 1e-6f);

        #pragma unroll
        for (int mm = 0; mm < 3; ++mm) {
            const int m = cpart + mm * 4;
            if (m < 11) {
                float lx, ly, lz;
                if (m == 0)      { lx = 0.f;  ly = 0.f;  lz = 0.f; }
                else if (m == 1) { lx = 0.f;  ly = sy;   lz = 0.f; }
                else if (m == 2) { lx = 0.f;  ly = -sy;  lz = 0.f; }
                else if (m == 3) { lx = sx;   ly = 0.f;  lz = 0.f; }
                else if (m == 4) { lx = -sx;  ly = 0.f;  lz = 0.f; }
                else {
                    const int j = (m - 5) * 3;
                    const float t0 = s[j]   + lfbs[j];
                    const float t1 = s[j+1] + lfbs[j+1];
                    const float t2 = s[j+2] + lfbs[j+2];
                    const float g0 = 1.f / (1.f + __expf(-t0));
                    const float g1 = 1.f / (1.f + __expf(-t1));
                    const float g2 = 1.f / (1.f + __expf(-t2));
                    lx = (g0 - 0.5f) * sx;
                    ly = (g1 - 0.5f) * sy;
                    lz = (g2 - 0.5f) * sz;
                }
                const float cxv = r00*lx + r01*ly + r02*lz + mx;
                const float cyv = r10*lx + r11*ly + r12*lz + my;
                const float czv = r20*lx + r21*ly + r22*lz + mz;
                const size_t cb = OUT_CORN + ((size_t)row * 11 + m) * 3;
                out[cb]   = cxv;
                out[cb+1] = cyv;
                out[cb+2] = czv;
                const float nx = fminf(fmaxf((cxv + 51.2f) * invxy, 0.f), 1.f);
                const float ny = fminf(fmaxf((cyv + 51.2f) * invxy, 0.f), 1.f);
                const float nz = fminf(fmaxf((czv + 5.0f)  * invz,  0.f), 1.f);
                const size_t rb = (size_t)row * 11 + m;
                out[OUT_XY + rb*2]     = nx;
                out[OUT_XY + rb*2 + 1] = ny;
                out[OUT_XZ + rb*2]     = nx;
                out[OUT_XZ + rb*2 + 1] = nz;
                out[OUT_YZ + rb*2]     = ny;
                out[OUT_YZ + rb*2 + 1] = nz;
            }
        }
    }
}

extern "C" void kernel_launch(void* const* d_in, const int* in_sizes, int n_in,
                              void* d_out, int out_size) {
    const float* mu    = (const float*)d_in[0];
    const float* sc    = (const float*)d_in[1];
    const float* rot   = (const float*)d_in[2];
    const float* Q     = (const float*)d_in[3];
    const float* w1    = (const float*)d_in[4];
    const float* b1    = (const float*)d_in[5];
    const float* gamma = (const float*)d_in[6];
    const float* beta  = (const float*)d_in[7];
    const float* w2    = (const float*)d_in[8];
    const float* b2    = (const float*)d_in[9];
    const float* lfw   = (const float*)d_in[10];
    const float* lfb   = (const float*)d_in[11];
    float* out = (float*)d_out;
    const int N = in_sizes[0] / 3;

    w2_convert_kernel<<<256, 256>>>(w2);

    const int smemA = SMEM_A_FLOATS * sizeof(float);
    const int smemB = SMEM_B_FLOATS * sizeof(float);
    cudaFuncSetAttribute(gauss_gemm_kernel,
                         cudaFuncAttributeMaxDynamicSharedMemorySize, smemA);
    cudaFuncSetAttribute(gauss_corner_kernel,
                         cudaFuncAttributeMaxDynamicSharedMemorySize, smemB);
    const int blocks = (N + MT - 1) / MT;
    gauss_gemm_kernel<<<blocks, 256, smemA>>>(
        mu, sc, rot, Q, w1, b1, gamma, beta, b2, out, N);
    gauss_corner_kernel<<<blocks, 256, smemB>>>(
        mu, sc, rot, lfw, lfb, out, N);
}

// round 5
// speedup vs baseline: 1.6212x; 1.1259x over previous
#include <cuda_runtime.h>
#include <cuda_fp16.h>
#include <mma.h>
#include <cstdint>

using namespace nvcuda;
typedef unsigned int u32;

#define MT 64
#define LDH 264            // fp16 per hs row (528B stride)
#define LDF 264            // fp32 per fs row (kernel A)
#define LDFB 260           // fp32 per fs row (kernel B)

// ---------------- kernel A smem (floats) ----------------
// hs: fp16[64*264]            = 8448 floats   [0, 8448)
// B : 2 bufs x (hi 16x264 + lo 16x264) fp16 = 8448 floats  [8448, 16896)
// fs: fp32[64*264] = 16896 floats OVERLAYS hs+B (both dead post-GEMM)
// w1s 2560 | b1s 256 | gms 256 | bts 256
#define HS_F   0
#define B_F    8448
#define W1S_F  16896
#define B1S_F  19456
#define GMS_F  19712
#define BTS_F  19968
#define SMEM_A_FLOATS 20224          // 80896 B -> 2 CTAs/SM easily

// ---------------- kernel B smem (floats) ----------------
#define FSB_F  0                     // 64 x 260
#define LFW_F  16640                 // 256 x 20
#define LFB_F  21760
#define SMEM_B_FLOATS 21792          // 87168 B (2 CTAs/SM)

__device__ __half g_w2hi[65536];   // [K=256][N=256]
__device__ __half g_w2lo[65536];

__device__ __forceinline__ u32 smem_u32(const void* p) {
    return (u32)__cvta_generic_to_shared(p);
}
__device__ __forceinline__ void cp_async16(u32 s, const void* g) {
    asm volatile("cp.async.cg.shared.global [%0], [%1], 16;" :: "r"(s), "l"(g));
}
__device__ __forceinline__ void cp_commit() { asm volatile("cp.async.commit_group;"); }
template<int NN> __device__ __forceinline__ void cp_wait() {
    asm volatile("cp.async.wait_group %0;" :: "n"(NN) : "memory");
}

__global__ void w2_convert_kernel(const float* __restrict__ w2) {
    const int k = blockIdx.x, n = threadIdx.x;
    const float x = w2[k * 256 + n];
    const __half h = __float2half(x);
    g_w2hi[k * 256 + n] = h;
    g_w2lo[k * 256 + n] = __float2half(x - __half2float(h));
}

// stage a 16-k-row chunk of w2 (hi+lo fp16) into buffer buf
__device__ __forceinline__ void load_chunk(u32 smb, int buf, int kt, int tid) {
    const u32 base = smb + B_F * 4 + buf * 16896;
    #pragma unroll
    for (int q = 0; q < 4; ++q) {
        const int idx = tid + 256 * q;          // 0..1023
        const int hm  = idx >> 9;               // 0=hi, 1=lo
        const int i   = idx & 511;
        const int r   = i >> 5;                 // k-row 0..15
        const int j   = i & 31;                 // 8-fp16 chunk
        const u32 dst = base + hm * 8448 + r * 528 + j * 16;
        const __half* src = (hm ? g_w2lo : g_w2hi) + (kt + r) * 256 + j * 8;
        cp_async16(dst, src);
    }
}

// =================== Kernel A: LN + GEMM + features ===================
__global__ void __launch_bounds__(256, 2)
gauss_gemm_kernel(const float* __restrict__ mu, const float* __restrict__ sc,
                  const float* __restrict__ rot, const float* __restrict__ Q,
                  const float* __restrict__ w1, const float* __restrict__ b1,
                  const float* __restrict__ gamma, const float* __restrict__ beta,
                  const float* __restrict__ b2,
                  float* __restrict__ out, int N)
{
    extern __shared__ float sm[];
    const u32 smb = smem_u32(sm);
    __half* hs  = (__half*)(sm + HS_F);
    float* fs   = sm + HS_F;          // overlays hs + B after GEMM
    float* w1s  = sm + W1S_F;
    float* b1s  = sm + B1S_F;
    float* gms  = sm + GMS_F;
    float* bts  = sm + BTS_F;

    const int tid  = threadIdx.x;
    const int lane = tid & 31;
    const int wid  = tid >> 5;
    const int rowBase = blockIdx.x * MT;

    // prefetch first two B chunks
    load_chunk(smb, 0, 0, tid);  cp_commit();
    load_chunk(smb, 1, 16, tid); cp_commit();

    // stage constants
    #pragma unroll
    for (int i = tid; i < 2560; i += 256) w1s[i] = w1[i];
    b1s[tid] = b1[tid]; gms[tid] = gamma[tid]; bts[tid] = beta[tid];
    __syncthreads();

    // ---- phase 1: h = relu(LN(geo@w1+b1)) -> hs fp16 ----
    #pragma unroll 1
    for (int ii = 0; ii < 8; ++ii) {
        const int rl  = wid * 8 + ii;
        const int row = rowBase + rl;
        const bool valid = (row < N);
        float g[10];
        if (valid) {
            g[0]=mu[row*3]; g[1]=mu[row*3+1]; g[2]=mu[row*3+2];
            g[3]=sc[row*3]; g[4]=sc[row*3+1]; g[5]=sc[row*3+2];
            g[6]=rot[row*4]; g[7]=rot[row*4+1]; g[8]=rot[row*4+2]; g[9]=rot[row*4+3];
        } else {
            #pragma unroll
            for (int i = 0; i < 10; ++i) g[i] = 0.f;
        }
        float hv[8]; float s = 0.f;
        #pragma unroll
        for (int jj = 0; jj < 8; ++jj) {
            const int d = lane + 32 * jj;
            float a = b1s[d];
            #pragma unroll
            for (int i = 0; i < 10; ++i) a = fmaf(g[i], w1s[i*256 + d], a);
            hv[jj] = a; s += a;
        }
        #pragma unroll
        for (int o = 16; o; o >>= 1) s += __shfl_xor_sync(0xffffffffu, s, o);
        const float mean = s * (1.f/256.f);
        float v = 0.f;
        #pragma unroll
        for (int jj = 0; jj < 8; ++jj) { float t = hv[jj] - mean; v = fmaf(t, t, v); }
        #pragma unroll
        for (int o = 16; o; o >>= 1) v += __shfl_xor_sync(0xffffffffu, v, o);
        const float inv = rsqrtf(v * (1.f/256.f) + 1e-5f);
        #pragma unroll
        for (int jj = 0; jj < 8; ++jj) {
            const int d = lane + 32 * jj;
            float t = (hv[jj] - mean) * inv * gms[d] + bts[d];
            t = fmaxf(t, 0.f);
            if (!valid) t = 0.f;
            hs[rl * LDH + d] = __float2half(t);
        }
    }
    __syncthreads();

    // ---- phase 2: E = h @ w2 via fp16 2-product wmma (16 chunks of k=16) ----
    const int wm = wid & 1;        // 2 warps along M (32 rows each)
    const int wn = wid >> 1;       // 4 warps along N (64 cols each)

    wmma::fragment<wmma::accumulator, 16,16,16, float> acc[2][4];
    #pragma unroll
    for (int mi = 0; mi < 2; ++mi)
        #pragma unroll
        for (int ni = 0; ni < 4; ++ni) wmma::fill_fragment(acc[mi][ni], 0.f);

    #pragma unroll 1
    for (int t = 0; t < 16; ++t) {
        if (t < 15) { cp_wait<1>(); } else { cp_wait<0>(); }
        __syncthreads();

        const int buf = t & 1;
        const __half* bhi = (const __half*)(sm + B_F) + buf * 8448;
        const __half* blo = bhi + 16 * LDH;
        const int kk = t * 16;

        wmma::fragment<wmma::matrix_a, 16,16,16, __half, wmma::row_major> a_hi[2];
        #pragma unroll
        for (int mi = 0; mi < 2; ++mi)
            wmma::load_matrix_sync(a_hi[mi], hs + (wm*32 + mi*16) * LDH + kk, LDH);

        #pragma unroll
        for (int ni = 0; ni < 4; ++ni) {
            wmma::fragment<wmma::matrix_b, 16,16,16, __half, wmma::row_major> b_hi, b_lo;
            wmma::load_matrix_sync(b_hi, bhi + wn*64 + ni*16, LDH);
            wmma::load_matrix_sync(b_lo, blo + wn*64 + ni*16, LDH);
            #pragma unroll
            for (int mi = 0; mi < 2; ++mi) {
                wmma::mma_sync(acc[mi][ni], a_hi[mi], b_hi, acc[mi][ni]);
                wmma::mma_sync(acc[mi][ni], a_hi[mi], b_lo, acc[mi][ni]);
            }
        }
        __syncthreads();
        if (t + 2 < 16) { load_chunk(smb, buf, (t + 2) * 16, tid); cp_commit(); }
    }
    __syncthreads();   // hs + B dead; fs takes over the whole region

    // ---- phase 3a: acc -> fs ----
    #pragma unroll
    for (int mi = 0; mi < 2; ++mi)
        #pragma unroll
        for (int ni = 0; ni < 4; ++ni)
            wmma::store_matrix_sync(fs + (wm*32 + mi*16) * LDF + wn*64 + ni*16,
                                    acc[mi][ni], LDF, wmma::mem_row_major);
    __syncthreads();

    // ---- phase 3b: features = E + b2 + Q (batched MLP=8) ----
    const float b2v = __ldg(&b2[tid]);
    #pragma unroll 1
    for (int rb = 0; rb < MT; rb += 8) {
        float qv[8];
        #pragma unroll
        for (int k = 0; k < 8; ++k) {
            const int row = rowBase + rb + k;
            qv[k] = (row < N) ? Q[(size_t)row * 256 + tid] : 0.f;
        }
        #pragma unroll
        for (int k = 0; k < 8; ++k) {
            const int row = rowBase + rb + k;
            if (row < N)
                out[(size_t)row * 256 + tid] = fs[(rb + k) * LDF + tid] + b2v + qv[k];
        }
    }
}

// =================== Kernel B: lf matmul + corners + refs ===================
__global__ void __launch_bounds__(256, 2)
gauss_corner_kernel(const float* __restrict__ mu, const float* __restrict__ sc,
                    const float* __restrict__ rot,
                    const float* __restrict__ lfw, const float* __restrict__ lfb,
                    float* __restrict__ out, int N)
{
    extern __shared__ float sm[];
    float* fs   = sm + FSB_F;     // 64 x 260
    float* lfws = sm + LFW_F;     // 256 x 20
    float* lfbs = sm + LFB_F;

    const int tid  = threadIdx.x;
    const int lane = tid & 31;
    const int wid  = tid >> 5;
    const int rowBase = blockIdx.x * MT;

    {
        const int c = tid;
        #pragma unroll
        for (int j = 0; j < 18; ++j) lfws[c*20 + j] = lfw[c*18 + j];
        lfws[c*20 + 18] = 0.f; lfws[c*20 + 19] = 0.f;
    }
    if (tid < 18) lfbs[tid] = lfb[tid];

    // stage feature tile (batched MLP=8)
    #pragma unroll 1
    for (int rb = 0; rb < MT; rb += 8) {
        float fv[8];
        #pragma unroll
        for (int k = 0; k < 8; ++k) {
            const int row = rowBase + rb + k;
            fv[k] = (row < N) ? out[(size_t)row * 256 + tid] : 0.f;
        }
        #pragma unroll
        for (int k = 0; k < 8; ++k)
            fs[(rb + k) * LDFB + tid] = fv[k];
    }
    __syncthreads();

    // phase 4: warp = 8 rows x 4 col-partitions
    const int rl    = wid * 8 + (lane >> 2);
    const int cpart = lane & 3;
    const int row   = rowBase + rl;
    float s[18];
    #pragma unroll
    for (int j = 0; j < 18; ++j) s[j] = 0.f;
    const int cbase = cpart * 64;
    #pragma unroll 1
    for (int u = 0; u < 64; u += 4) {
        float4 fv = *(const float4*)&fs[rl * LDFB + cbase + u];
        const float fvals[4] = {fv.x, fv.y, fv.z, fv.w};
        #pragma unroll
        for (int p = 0; p < 4; ++p) {
            const float f = fvals[p];
            const int c = cbase + u + p;
            const float4 l0 = *(const float4*)&lfws[c*20 + 0];
            const float4 l1 = *(const float4*)&lfws[c*20 + 4];
            const float4 l2 = *(const float4*)&lfws[c*20 + 8];
            const float4 l3 = *(const float4*)&lfws[c*20 + 12];
            const float2 l4 = *(const float2*)&lfws[c*20 + 16];
            s[0]  = fmaf(f, l0.x, s[0]);  s[1]  = fmaf(f, l0.y, s[1]);
            s[2]  = fmaf(f, l0.z, s[2]);  s[3]  = fmaf(f, l0.w, s[3]);
            s[4]  = fmaf(f, l1.x, s[4]);  s[5]  = fmaf(f, l1.y, s[5]);
            s[6]  = fmaf(f, l1.z, s[6]);  s[7]  = fmaf(f, l1.w, s[7]);
            s[8]  = fmaf(f, l2.x, s[8]);  s[9]  = fmaf(f, l2.y, s[9]);
            s[10] = fmaf(f, l2.z, s[10]); s[11] = fmaf(f, l2.w, s[11]);
            s[12] = fmaf(f, l3.x, s[12]); s[13] = fmaf(f, l3.y, s[13]);
            s[14] = fmaf(f, l3.z, s[14]); s[15] = fmaf(f, l3.w, s[15]);
            s[16] = fmaf(f, l4.x, s[16]); s[17] = fmaf(f, l4.y, s[17]);
        }
    }
    #pragma unroll
    for (int j = 0; j < 18; ++j) {
        s[j] += __shfl_xor_sync(0xffffffffu, s[j], 1);
        s[j] += __shfl_xor_sync(0xffffffffu, s[j], 2);
    }

    if (row < N) {
        const float mx = mu[row*3], my = mu[row*3+1], mz = mu[row*3+2];
        const float sx = sc[row*3]*0.5f, sy = sc[row*3+1]*0.5f, sz = sc[row*3+2]*0.5f;
        float qw = rot[row*4], qx = rot[row*4+1], qy = rot[row*4+2], qz = rot[row*4+3];
        const float nrm = fmaxf(sqrtf(qw*qw + qx*qx + qy*qy + qz*qz), 1e-8f);
        const float inr = 1.f / nrm;
        qw *= inr; qx *= inr; qy *= inr; qz *= inr;
        const float r00 = 1.f - 2.f*(qy*qy + qz*qz), r01 = 2.f*(qx*qy - qz*qw), r02 = 2.f*(qx*qz + qy*qw);
        const float r10 = 2.f*(qx*qy + qz*qw), r11 = 1.f - 2.f*(qx*qx + qz*qz), r12 = 2.f*(qy*qz - qx*qw);
        const float r20 = 2.f*(qx*qz - qy*qw), r21 = 2.f*(qy*qz + qx*qw), r22 = 1.f - 2.f*(qx*qx + qy*qy);

        const size_t OUT_CORN = (size_t)N * 256;
        const size_t OUT_XY   = OUT_CORN + (size_t)N * 33;
        const size_t OUT_XZ   = OUT_XY + (size_t)N * 22;
        const size_t OUT_YZ   = OUT_XZ + (size_t)N * 22;
        const float invxy = 1.f / (102.4f + 1e-6f);
        const float invz  = 1.f / (8.0f + 1e-6f);

        #pragma unroll
        for (int mm = 0; mm < 3; ++mm) {
            const int m = cpart + mm * 4;
            if (m < 11) {
                float lx, ly, lz;
                if (m == 0)      { lx = 0.f;  ly = 0.f;  lz = 0.f; }
                else if (m == 1) { lx = 0.f;  ly = sy;   lz = 0.f; }
                else if (m == 2) { lx = 0.f;  ly = -sy;  lz = 0.f; }
                else if (m == 3) { lx = sx;   ly = 0.f;  lz = 0.f; }
                else if (m == 4) { lx = -sx;  ly = 0.f;  lz = 0.f; }
                else {
                    const int j = (m - 5) * 3;
                    const float t0 = s[j]   + lfbs[j];
                    const float t1 = s[j+1] + lfbs[j+1];
                    const float t2 = s[j+2] + lfbs[j+2];
                    const float g0 = 1.f / (1.f + __expf(-t0));
                    const float g1 = 1.f / (1.f + __expf(-t1));
                    const float g2 = 1.f / (1.f + __expf(-t2));
                    lx = (g0 - 0.5f) * sx;
                    ly = (g1 - 0.5f) * sy;
                    lz = (g2 - 0.5f) * sz;
                }
                const float cxv = r00*lx + r01*ly + r02*lz + mx;
                const float cyv = r10*lx + r11*ly + r12*lz + my;
                const float czv = r20*lx + r21*ly + r22*lz + mz;
                const size_t cb = OUT_CORN + ((size_t)row * 11 + m) * 3;
                out[cb]   = cxv;
                out[cb+1] = cyv;
                out[cb+2] = czv;
                const float nx = fminf(fmaxf((cxv + 51.2f) * invxy, 0.f), 1.f);
                const float ny = fminf(fmaxf((cyv + 51.2f) * invxy, 0.f), 1.f);
                const float nz = fminf(fmaxf((czv + 5.0f)  * invz,  0.f), 1.f);
                const size_t rb = (size_t)row * 11 + m;
                out[OUT_XY + rb*2]     = nx;
                out[OUT_XY + rb*2 + 1] = ny;
                out[OUT_XZ + rb*2]     = nx;
                out[OUT_XZ + rb*2 + 1] = nz;
                out[OUT_YZ + rb*2]     = ny;
                out[OUT_YZ + rb*2 + 1] = nz;
            }
        }
    }
}

extern "C" void kernel_launch(void* const* d_in, const int* in_sizes, int n_in,
                              void* d_out, int out_size) {
    const float* mu    = (const float*)d_in[0];
    const float* sc    = (const float*)d_in[1];
    const float* rot   = (const float*)d_in[2];
    const float* Q     = (const float*)d_in[3];
    const float* w1    = (const float*)d_in[4];
    const float* b1    = (const float*)d_in[5];
    const float* gamma = (const float*)d_in[6];
    const float* beta  = (const float*)d_in[7];
    const float* w2    = (const float*)d_in[8];
    const float* b2    = (const float*)d_in[9];
    const float* lfw   = (const float*)d_in[10];
    const float* lfb   = (const float*)d_in[11];
    float* out = (float*)d_out;
    const int N = in_sizes[0] / 3;

    w2_convert_kernel<<<256, 256>>>(w2);

    const int smemA = SMEM_A_FLOATS * sizeof(float);
    const int smemB = SMEM_B_FLOATS * sizeof(float);
    cudaFuncSetAttribute(gauss_gemm_kernel,
                         cudaFuncAttributeMaxDynamicSharedMemorySize, smemA);
    cudaFuncSetAttribute(gauss_corner_kernel,
                         cudaFuncAttributeMaxDynamicSharedMemorySize, smemB);
    const int blocks = (N + MT - 1) / MT;
    gauss_gemm_kernel<<<blocks, 256, smemA>>>(
        mu, sc, rot, Q, w1, b1, gamma, beta, b2, out, N);
    gauss_corner_kernel<<<blocks, 256, smemB>>>(
        mu, sc, rot, lfw, lfb, out, N);
}

// round 6
// speedup vs baseline: 1.6808x; 1.0367x over previous
#include <cuda_runtime.h>
#include <cuda_fp16.h>
#include <mma.h>
#include <cstdint>

using namespace nvcuda;
typedef unsigned int u32;

#define MT 64
#define LDH 280            // hs fp16 stride (560B rows; >=272, mult of 8; conflict-free ldmatrix)
#define LDB 264            // B fp16 stride (528B rows)
#define LDFB 260           // fp32 per fs row (kernel B)
#define KAUG 272           // K extended by 16 (row 256 = b2, 257-271 = 0)
#define NCHUNK 17          // 272 / 16

// ---------------- kernel A smem (floats) ----------------
// hs: 64 x 280 fp16 = 8960 floats           [0, 8960)
// B : 3 bufs x (hi 16x264 + lo 16x264) fp16 = 12672 floats  [8960, 21632)
// w1s 2560 | b1s 256 | gms 256 | bts 256
#define HS_F   0
#define B_F    8960
#define W1S_F  21632
#define B1S_F  24192
#define GMS_F  24448
#define BTS_F  24704
#define SMEM_A_FLOATS 24960          // 99840 B -> 2 CTAs/SM

// ---------------- kernel B smem (floats) ----------------
#define FSB_F  0                     // 64 x 260
#define LFW_F  16640                 // 256 x 20
#define LFB_F  21760
#define SMEM_B_FLOATS 21792

__device__ __half g_w2hi[KAUG * 256];   // [K=272][N=256]
__device__ __half g_w2lo[KAUG * 256];

__device__ __forceinline__ u32 smem_u32(const void* p) {
    return (u32)__cvta_generic_to_shared(p);
}
__device__ __forceinline__ void cp_async16(u32 s, const void* g) {
    asm volatile("cp.async.cg.shared.global [%0], [%1], 16;" :: "r"(s), "l"(g));
}
__device__ __forceinline__ void cp_commit() { asm volatile("cp.async.commit_group;"); }
template<int NN> __device__ __forceinline__ void cp_wait() {
    asm volatile("cp.async.wait_group %0;" :: "n"(NN) : "memory");
}

__global__ void w2_convert_kernel(const float* __restrict__ w2,
                                  const float* __restrict__ b2) {
    const int k = blockIdx.x, n = threadIdx.x;
    const float x = (k < 256) ? w2[k * 256 + n] : (k == 256 ? b2[n] : 0.f);
    const __half h = __float2half(x);
    g_w2hi[k * 256 + n] = h;
    g_w2lo[k * 256 + n] = __float2half(x - __half2float(h));
}

// stage a 16-k-row chunk of w2 (hi+lo fp16) into buffer buf (0..2)
__device__ __forceinline__ void load_chunk(u32 smb, int buf, int kt, int tid) {
    const u32 base = smb + B_F * 4 + buf * 16896;
    #pragma unroll
    for (int q = 0; q < 4; ++q) {
        const int idx = tid + 256 * q;          // 0..1023
        const int hm  = idx >> 9;               // 0=hi, 1=lo
        const int i   = idx & 511;
        const int r   = i >> 5;                 // k-row 0..15
        const int j   = i & 31;                 // 8-fp16 chunk
        const u32 dst = base + hm * 8448 + r * 528 + j * 16;
        const __half* src = (hm ? g_w2lo : g_w2hi) + (kt + r) * 256 + j * 8;
        cp_async16(dst, src);
    }
}

// =================== Kernel A: LN + GEMM + fragment epilogue ===================
__global__ void __launch_bounds__(256, 2)
gauss_gemm_kernel(const float* __restrict__ mu, const float* __restrict__ sc,
                  const float* __restrict__ rot, const float* __restrict__ Q,
                  const float* __restrict__ w1, const float* __restrict__ b1,
                  const float* __restrict__ gamma, const float* __restrict__ beta,
                  float* __restrict__ out, int N)
{
    extern __shared__ float sm[];
    const u32 smb = smem_u32(sm);
    __half* hs  = (__half*)(sm + HS_F);
    float* w1s  = sm + W1S_F;
    float* b1s  = sm + B1S_F;
    float* gms  = sm + GMS_F;
    float* bts  = sm + BTS_F;

    const int tid  = threadIdx.x;
    const int lane = tid & 31;
    const int wid  = tid >> 5;
    const int rowBase = blockIdx.x * MT;

    // prefetch first two B chunks
    load_chunk(smb, 0, 0, tid);  cp_commit();
    load_chunk(smb, 1, 16, tid); cp_commit();

    // stage constants
    #pragma unroll
    for (int i = tid; i < 2560; i += 256) w1s[i] = w1[i];
    b1s[tid] = b1[tid]; gms[tid] = gamma[tid]; bts[tid] = beta[tid];

    // hs augmentation columns: col 256 = 1.0, cols 257-271 = 0
    {
        const int r = tid >> 2;           // 0..63
        const int c = 256 + (tid & 3) * 4;
        __half* p = hs + r * LDH + c;
        p[0] = (c == 256) ? __float2half(1.f) : __float2half(0.f);
        p[1] = __float2half(0.f);
        p[2] = __float2half(0.f);
        p[3] = __float2half(0.f);
    }
    __syncthreads();

    // ---- phase 1: h = relu(LN(geo@w1+b1)) -> hs fp16 ; 4-row batches ----
    #pragma unroll 1
    for (int bb = 0; bb < 2; ++bb) {
        const int rl0 = wid * 8 + bb * 4;
        float g[4][10];
        #pragma unroll
        for (int r = 0; r < 4; ++r) {
            const int row = rowBase + rl0 + r;
            if (row < N) {
                g[r][0]=mu[row*3]; g[r][1]=mu[row*3+1]; g[r][2]=mu[row*3+2];
                g[r][3]=sc[row*3]; g[r][4]=sc[row*3+1]; g[r][5]=sc[row*3+2];
                g[r][6]=rot[row*4]; g[r][7]=rot[row*4+1]; g[r][8]=rot[row*4+2]; g[r][9]=rot[row*4+3];
            } else {
                #pragma unroll
                for (int i = 0; i < 10; ++i) g[r][i] = 0.f;
            }
        }
        float hv[4][8];
        #pragma unroll
        for (int jj = 0; jj < 8; ++jj) {
            const int d = lane + 32 * jj;
            float w[10];
            #pragma unroll
            for (int i = 0; i < 10; ++i) w[i] = w1s[i*256 + d];
            const float bv = b1s[d];
            #pragma unroll
            for (int r = 0; r < 4; ++r) {
                float a = bv;
                #pragma unroll
                for (int i = 0; i < 10; ++i) a = fmaf(g[r][i], w[i], a);
                hv[r][jj] = a;
            }
        }
        float s[4] = {0.f, 0.f, 0.f, 0.f};
        #pragma unroll
        for (int r = 0; r < 4; ++r)
            #pragma unroll
            for (int jj = 0; jj < 8; ++jj) s[r] += hv[r][jj];
        #pragma unroll
        for (int o = 16; o; o >>= 1) {
            #pragma unroll
            for (int r = 0; r < 4; ++r) s[r] += __shfl_xor_sync(0xffffffffu, s[r], o);
        }
        float v[4] = {0.f, 0.f, 0.f, 0.f};
        float mean[4];
        #pragma unroll
        for (int r = 0; r < 4; ++r) {
            mean[r] = s[r] * (1.f/256.f);
            #pragma unroll
            for (int jj = 0; jj < 8; ++jj) { float t = hv[r][jj] - mean[r]; v[r] = fmaf(t, t, v[r]); }
        }
        #pragma unroll
        for (int o = 16; o; o >>= 1) {
            #pragma unroll
            for (int r = 0; r < 4; ++r) v[r] += __shfl_xor_sync(0xffffffffu, v[r], o);
        }
        #pragma unroll
        for (int r = 0; r < 4; ++r) {
            const float inv = rsqrtf(v[r] * (1.f/256.f) + 1e-5f);
            const bool valid = (rowBase + rl0 + r < N);
            #pragma unroll
            for (int jj = 0; jj < 8; ++jj) {
                const int d = lane + 32 * jj;
                float t = (hv[r][jj] - mean[r]) * inv * gms[d] + bts[d];
                t = fmaxf(t, 0.f);
                if (!valid) t = 0.f;
                hs[(rl0 + r) * LDH + d] = __float2half(t);
            }
        }
    }
    __syncthreads();

    // ---- phase 2: E+b2 = h_aug @ w2_aug ; warp tile 64x32, 17 chunks, 3 bufs ----
    const int wn = wid;               // warp's 32-col slab
    const int c0 = wn * 32;

    wmma::fragment<wmma::accumulator, 16,16,16, float> acc[4][2];
    #pragma unroll
    for (int mi = 0; mi < 4; ++mi)
        #pragma unroll
        for (int ni = 0; ni < 2; ++ni) wmma::fill_fragment(acc[mi][ni], 0.f);

    #pragma unroll 1
    for (int t = 0; t < NCHUNK; ++t) {
        if (t + 2 < NCHUNK) { cp_wait<1>(); } else { cp_wait<0>(); }
        __syncthreads();
        if (t + 2 < NCHUNK) { load_chunk(smb, (t + 2) % 3, (t + 2) * 16, tid); cp_commit(); }

        const __half* bhi = (const __half*)(sm + B_F) + (t % 3) * 8448;
        const __half* blo = bhi + 16 * LDB;
        const int kk = t * 16;

        wmma::fragment<wmma::matrix_a, 16,16,16, __half, wmma::row_major> a[4];
        #pragma unroll
        for (int mi = 0; mi < 4; ++mi)
            wmma::load_matrix_sync(a[mi], hs + (mi*16) * LDH + kk, LDH);

        #pragma unroll
        for (int ni = 0; ni < 2; ++ni) {
            wmma::fragment<wmma::matrix_b, 16,16,16, __half, wmma::row_major> bh, bl;
            wmma::load_matrix_sync(bh, bhi + c0 + ni*16, LDB);
            wmma::load_matrix_sync(bl, blo + c0 + ni*16, LDB);
            #pragma unroll
            for (int mi = 0; mi < 4; ++mi) {
                wmma::mma_sync(acc[mi][ni], a[mi], bh, acc[mi][ni]);
                wmma::mma_sync(acc[mi][ni], a[mi], bl, acc[mi][ni]);
            }
        }
    }

    // ---- epilogue: features = acc + Q, straight from fragments ----
    if (rowBase + MT <= N) {
        #pragma unroll
        for (int mi = 0; mi < 4; ++mi) {
            #pragma unroll
            for (int ni = 0; ni < 2; ++ni) {
                const size_t goff = (size_t)(rowBase + mi*16) * 256 + c0 + ni*16;
                wmma::fragment<wmma::accumulator, 16,16,16, float> qf;
                wmma::load_matrix_sync(qf, Q + goff, 256, wmma::mem_row_major);
                #pragma unroll
                for (int e = 0; e < qf.num_elements; ++e) acc[mi][ni].x[e] += qf.x[e];
                wmma::store_matrix_sync(out + goff, acc[mi][ni], 256, wmma::mem_row_major);
            }
        }
    } else {
        // tail CTA: stage each 16x16 tile through private smem scratch
        __syncthreads();                       // B bufs now free
        float* scr = sm + B_F + wid * 256;     // 1KB per warp
        #pragma unroll 1
        for (int mi = 0; mi < 4; ++mi) {
            #pragma unroll 1
            for (int ni = 0; ni < 2; ++ni) {
                wmma::store_matrix_sync(scr, acc[mi][ni], 16, wmma::mem_row_major);
                __syncwarp();
                const int r0 = rowBase + mi*16;
                #pragma unroll
                for (int idx = 0; idx < 8; ++idx) {
                    const int e  = lane + idx * 32;
                    const int rr = e >> 4, cc = e & 15;
                    if (r0 + rr < N) {
                        const size_t goff = (size_t)(r0 + rr) * 256 + c0 + ni*16 + cc;
                        out[goff] = scr[e] + Q[goff];
                    }
                }
                __syncwarp();
            }
        }
    }
}

// =================== Kernel B: lf matmul + corners + refs ===================
__global__ void __launch_bounds__(256, 2)
gauss_corner_kernel(const float* __restrict__ mu, const float* __restrict__ sc,
                    const float* __restrict__ rot,
                    const float* __restrict__ lfw, const float* __restrict__ lfb,
                    float* __restrict__ out, int N)
{
    extern __shared__ float sm[];
    float* fs   = sm + FSB_F;     // 64 x 260
    float* lfws = sm + LFW_F;     // 256 x 20
    float* lfbs = sm + LFB_F;

    const int tid  = threadIdx.x;
    const int lane = tid & 31;
    const int wid  = tid >> 5;
    const int rowBase = blockIdx.x * MT;

    {
        const int c = tid;
        #pragma unroll
        for (int j = 0; j < 18; ++j) lfws[c*20 + j] = lfw[c*18 + j];
        lfws[c*20 + 18] = 0.f; lfws[c*20 + 19] = 0.f;
    }
    if (tid < 18) lfbs[tid] = lfb[tid];

    #pragma unroll 1
    for (int rb = 0; rb < MT; rb += 8) {
        float fv[8];
        #pragma unroll
        for (int k = 0; k < 8; ++k) {
            const int row = rowBase + rb + k;
            fv[k] = (row < N) ? out[(size_t)row * 256 + tid] : 0.f;
        }
        #pragma unroll
        for (int k = 0; k < 8; ++k)
            fs[(rb + k) * LDFB + tid] = fv[k];
    }
    __syncthreads();

    const int rl    = wid * 8 + (lane >> 2);
    const int cpart = lane & 3;
    const int row   = rowBase + rl;
    float s[18];
    #pragma unroll
    for (int j = 0; j < 18; ++j) s[j] = 0.f;
    const int cbase = cpart * 64;
    #pragma unroll 1
    for (int u = 0; u < 64; u += 4) {
        float4 fv = *(const float4*)&fs[rl * LDFB + cbase + u];
        const float fvals[4] = {fv.x, fv.y, fv.z, fv.w};
        #pragma unroll
        for (int p = 0; p < 4; ++p) {
            const float f = fvals[p];
            const int c = cbase + u + p;
            const float4 l0 = *(const float4*)&lfws[c*20 + 0];
            const float4 l1 = *(const float4*)&lfws[c*20 + 4];
            const float4 l2 = *(const float4*)&lfws[c*20 + 8];
            const float4 l3 = *(const float4*)&lfws[c*20 + 12];
            const float2 l4 = *(const float2*)&lfws[c*20 + 16];
            s[0]  = fmaf(f, l0.x, s[0]);  s[1]  = fmaf(f, l0.y, s[1]);
            s[2]  = fmaf(f, l0.z, s[2]);  s[3]  = fmaf(f, l0.w, s[3]);
            s[4]  = fmaf(f, l1.x, s[4]);  s[5]  = fmaf(f, l1.y, s[5]);
            s[6]  = fmaf(f, l1.z, s[6]);  s[7]  = fmaf(f, l1.w, s[7]);
            s[8]  = fmaf(f, l2.x, s[8]);  s[9]  = fmaf(f, l2.y, s[9]);
            s[10] = fmaf(f, l2.z, s[10]); s[11] = fmaf(f, l2.w, s[11]);
            s[12] = fmaf(f, l3.x, s[12]); s[13] = fmaf(f, l3.y, s[13]);
            s[14] = fmaf(f, l3.z, s[14]); s[15] = fmaf(f, l3.w, s[15]);
            s[16] = fmaf(f, l4.x, s[16]); s[17] = fmaf(f, l4.y, s[17]);
        }
    }
    #pragma unroll
    for (int j = 0; j < 18; ++j) {
        s[j] += __shfl_xor_sync(0xffffffffu, s[j], 1);
        s[j] += __shfl_xor_sync(0xffffffffu, s[j], 2);
    }

    if (row < N) {
        const float mx = mu[row*3], my = mu[row*3+1], mz = mu[row*3+2];
        const float sx = sc[row*3]*0.5f, sy = sc[row*3+1]*0.5f, sz = sc[row*3+2]*0.5f;
        float qw = rot[row*4], qx = rot[row*4+1], qy = rot[row*4+2], qz = rot[row*4+3];
        const float nrm = fmaxf(sqrtf(qw*qw + qx*qx + qy*qy + qz*qz), 1e-8f);
        const float inr = 1.f / nrm;
        qw *= inr; qx *= inr; qy *= inr; qz *= inr;
        const float r00 = 1.f - 2.f*(qy*qy + qz*qz), r01 = 2.f*(qx*qy - qz*qw), r02 = 2.f*(qx*qz + qy*qw);
        const float r10 = 2.f*(qx*qy + qz*qw), r11 = 1.f - 2.f*(qx*qx + qz*qz), r12 = 2.f*(qy*qz - qx*qw);
        const float r20 = 2.f*(qx*qz - qy*qw), r21 = 2.f*(qy*qz + qx*qw), r22 = 1.f - 2.f*(qx*qx + qy*qy);

        const size_t OUT_CORN = (size_t)N * 256;
        const size_t OUT_XY   = OUT_CORN + (size_t)N * 33;
        const size_t OUT_XZ   = OUT_XY + (size_t)N * 22;
        const size_t OUT_YZ   = OUT_XZ + (size_t)N * 22;
        const float invxy = 1.f / (102.4f + 1e-6f);
        const float invz  = 1.f / (8.0f + 1e-6f);

        #pragma unroll
        for (int mm = 0; mm < 3; ++mm) {
            const int m = cpart + mm * 4;
            if (m < 11) {
                float lx, ly, lz;
                if (m == 0)      { lx = 0.f;  ly = 0.f;  lz = 0.f; }
                else if (m == 1) { lx = 0.f;  ly = sy;   lz = 0.f; }
                else if (m == 2) { lx = 0.f;  ly = -sy;  lz = 0.f; }
                else if (m == 3) { lx = sx;   ly = 0.f;  lz = 0.f; }
                else if (m == 4) { lx = -sx;  ly = 0.f;  lz = 0.f; }
                else {
                    const int j = (m - 5) * 3;
                    const float t0 = s[j]   + lfbs[j];
                    const float t1 = s[j+1] + lfbs[j+1];
                    const float t2 = s[j+2] + lfbs[j+2];
                    const float g0 = 1.f / (1.f + __expf(-t0));
                    const float g1 = 1.f / (1.f + __expf(-t1));
                    const float g2 = 1.f / (1.f + __expf(-t2));
                    lx = (g0 - 0.5f) * sx;
                    ly = (g1 - 0.5f) * sy;
                    lz = (g2 - 0.5f) * sz;
                }
                const float cxv = r00*lx + r01*ly + r02*lz + mx;
                const float cyv = r10*lx + r11*ly + r12*lz + my;
                const float czv = r20*lx + r21*ly + r22*lz + mz;
                const size_t cb = OUT_CORN + ((size_t)row * 11 + m) * 3;
                out[cb]   = cxv;
                out[cb+1] = cyv;
                out[cb+2] = czv;
                const float nx = fminf(fmaxf((cxv + 51.2f) * invxy, 0.f), 1.f);
                const float ny = fminf(fmaxf((cyv + 51.2f) * invxy, 0.f), 1.f);
                const float nz = fminf(fmaxf((czv + 5.0f)  * invz,  0.f), 1.f);
                const size_t rb2 = (size_t)row * 11 + m;
                out[OUT_XY + rb2*2]     = nx;
                out[OUT_XY + rb2*2 + 1] = ny;
                out[OUT_XZ + rb2*2]     = nx;
                out[OUT_XZ + rb2*2 + 1] = nz;
                out[OUT_YZ + rb2*2]     = ny;
                out[OUT_YZ + rb2*2 + 1] = nz;
            }
        }
    }
}

extern "C" void kernel_launch(void* const* d_in, const int* in_sizes, int n_in,
                              void* d_out, int out_size) {
    const float* mu    = (const float*)d_in[0];
    const float* sc    = (const float*)d_in[1];
    const float* rot   = (const float*)d_in[2];
    const float* Q     = (const float*)d_in[3];
    const float* w1    = (const float*)d_in[4];
    const float* b1    = (const float*)d_in[5];
    const float* gamma = (const float*)d_in[6];
    const float* beta  = (const float*)d_in[7];
    const float* w2    = (const float*)d_in[8];
    const float* b2    = (const float*)d_in[9];
    const float* lfw   = (const float*)d_in[10];
    const float* lfb   = (const float*)d_in[11];
    float* out = (float*)d_out;
    const int N = in_sizes[0] / 3;

    w2_convert_kernel<<<KAUG, 256>>>(w2, b2);

    const int smemA = SMEM_A_FLOATS * sizeof(float);
    const int smemB = SMEM_B_FLOATS * sizeof(float);
    cudaFuncSetAttribute(gauss_gemm_kernel,
                         cudaFuncAttributeMaxDynamicSharedMemorySize, smemA);
    cudaFuncSetAttribute(gauss_corner_kernel,
                         cudaFuncAttributeMaxDynamicSharedMemorySize, smemB);
    const int blocks = (N + MT - 1) / MT;
    gauss_gemm_kernel<<<blocks, 256, smemA>>>(
        mu, sc, rot, Q, w1, b1, gamma, beta, out, N);
    gauss_corner_kernel<<<blocks, 256, smemB>>>(
        mu, sc, rot, lfw, lfb, out, N);
}

// round 7
// speedup vs baseline: 1.7783x; 1.0580x over previous
#include <cuda_runtime.h>
#include <cuda_fp16.h>
#include <mma.h>
#include <cstdint>

using namespace nvcuda;
typedef unsigned int u32;

#define MT 64
#define LDH 280            // hs fp16 stride
#define LDB 264            // B fp16 stride
#define LDFS 260           // fs fp32 stride
#define KAUG 272           // K + 16 (row 256 = b2)
#define NCHUNK 17

// ---------------- smem layout (floats) ----------------
// hs: 64 x 280 fp16 = 8960 floats       [0, 8960)
// B : 3 bufs x 4224 = 12672 floats      [8960, 21632)
// fs: 64 x 260 fp32 = 16640 floats      overlay [0, 16640) post-GEMM
// geo: mus 192 | scs 192 | rots 256     [21632, 22272)
// lfws 5120                             [22272, 27392)
// lfbs 32                               [27392, 27424)
#define HS_F   0
#define B_F    8960
#define GEO_F  21632
#define LFW_F  22272
#define LFB_F  27392
#define SMEM_FLOATS 27424            // 109,696 B -> 2 CTAs/SM

__device__ __half g_w2hi[KAUG * 256];   // [K=272][N=256]
__device__ __half g_w2lo[KAUG * 256];
__device__ float  g_lfwp[256 * 20];     // lfw padded to stride 20

__device__ __forceinline__ u32 smem_u32(const void* p) {
    return (u32)__cvta_generic_to_shared(p);
}
__device__ __forceinline__ void cp_async16(u32 s, const void* g) {
    asm volatile("cp.async.cg.shared.global [%0], [%1], 16;" :: "r"(s), "l"(g));
}
__device__ __forceinline__ void cp_commit() { asm volatile("cp.async.commit_group;"); }
template<int NN> __device__ __forceinline__ void cp_wait() {
    asm volatile("cp.async.wait_group %0;" :: "n"(NN) : "memory");
}

__global__ void w2_convert_kernel(const float* __restrict__ w2,
                                  const float* __restrict__ b2,
                                  const float* __restrict__ lfw) {
    const int k = blockIdx.x, n = threadIdx.x;
    const float x = (k < 256) ? w2[k * 256 + n] : (k == 256 ? b2[n] : 0.f);
    const __half h = __float2half(x);
    g_w2hi[k * 256 + n] = h;
    g_w2lo[k * 256 + n] = __float2half(x - __half2float(h));
    if (k < 18)       g_lfwp[n * 20 + k] = lfw[n * 18 + k];
    else if (k < 20)  g_lfwp[n * 20 + k] = 0.f;
}

// stage a 16-k-row chunk of w2 (hi+lo fp16) into buffer buf (0..2)
__device__ __forceinline__ void load_chunk(u32 smb, int buf, int kt, int tid) {
    const u32 base = smb + B_F * 4 + buf * 16896;
    #pragma unroll
    for (int q = 0; q < 4; ++q) {
        const int idx = tid + 256 * q;          // 0..1023
        const int hm  = idx >> 9;               // 0=hi, 1=lo
        const int i   = idx & 511;
        const int r   = i >> 5;                 // k-row 0..15
        const int j   = i & 31;                 // 8-fp16 chunk
        const u32 dst = base + hm * 8448 + r * 528 + j * 16;
        const __half* src = (hm ? g_w2lo : g_w2hi) + (kt + r) * 256 + j * 8;
        cp_async16(dst, src);
    }
}

// =================== Fused kernel ===================
__global__ void __launch_bounds__(256, 2)
gauss_fused_kernel(const float* __restrict__ mu, const float* __restrict__ sc,
                   const float* __restrict__ rot, const float* __restrict__ Q,
                   const float* __restrict__ w1, const float* __restrict__ b1,
                   const float* __restrict__ gamma, const float* __restrict__ beta,
                   const float* __restrict__ lfb,
                   float* __restrict__ out, int N)
{
    extern __shared__ float sm[];
    const u32 smb = smem_u32(sm);
    __half* hs  = (__half*)(sm + HS_F);
    float* fs   = sm + HS_F;            // overlay post-GEMM
    float* mus  = sm + GEO_F;           // 192
    float* scs  = sm + GEO_F + 192;     // 192
    float* rots = sm + GEO_F + 384;     // 256
    float* lfws = sm + LFW_F;
    float* lfbs = sm + LFB_F;

    const int tid  = threadIdx.x;
    const int lane = tid & 31;
    const int wid  = tid >> 5;
    const int rowBase = blockIdx.x * MT;
    const bool fullTile = (rowBase + MT <= N);

    // ---- group G: lfw (padded) + geo ----
    {
        const u32 lfdst = smb + LFW_F * 4;
        #pragma unroll
        for (int q = 0; q < 5; ++q) {
            const int c = tid + 256 * q;      // 0..1279 chunks of 16B
            cp_async16(lfdst + c * 16, g_lfwp + c * 4);
        }
        if (fullTile) {
            if (tid < 48)
                cp_async16(smb + (GEO_F + tid * 4) * 4, mu + (size_t)rowBase * 3 + tid * 4);
            else if (tid >= 64 && tid < 112)
                cp_async16(smb + (GEO_F + 192 + (tid - 64) * 4) * 4, sc + (size_t)rowBase * 3 + (tid - 64) * 4);
            else if (tid >= 128 && tid < 192)
                cp_async16(smb + (GEO_F + 384 + (tid - 128) * 4) * 4, rot + (size_t)rowBase * 4 + (tid - 128) * 4);
        } else {
            #pragma unroll 1
            for (int idx = tid; idx < 640; idx += 256) {
                float v = 0.f;
                if (idx < 192)      { const int r = idx / 3;        if (rowBase + r < N) v = mu[(size_t)(rowBase + r) * 3 + idx % 3]; }
                else if (idx < 384) { const int r = (idx - 192) / 3; if (rowBase + r < N) v = sc[(size_t)(rowBase + r) * 3 + (idx - 192) % 3]; }
                else                { const int r = (idx - 384) / 4; if (rowBase + r < N) v = rot[(size_t)(rowBase + r) * 4 + (idx - 384) % 4]; }
                sm[GEO_F + idx] = v;
            }
        }
    }
    cp_commit();                                    // [G]
    load_chunk(smb, 0, 0, tid);  cp_commit();       // [G][B0]
    load_chunk(smb, 1, 16, tid); cp_commit();       // [G][B0][B1]

    if (tid < 18) lfbs[tid] = lfb[tid];

    // hs augmentation columns: col 256 = 1.0, cols 257-271 = 0
    {
        const int r = tid >> 2;
        const int c = 256 + (tid & 3) * 4;
        __half* p = hs + r * LDH + c;
        p[0] = (c == 256) ? __float2half(1.f) : __float2half(0.f);
        p[1] = __float2half(0.f);
        p[2] = __float2half(0.f);
        p[3] = __float2half(0.f);
    }

    cp_wait<2>();          // G done; B0,B1 in flight
    __syncthreads();

    // ---- phase 1: h = relu(LN(geo@w1+b1)) -> hs fp16 ; 4-row batches ----
    #pragma unroll 1
    for (int bb = 0; bb < 2; ++bb) {
        const int rl0 = wid * 8 + bb * 4;
        float g[4][10];
        #pragma unroll
        for (int r = 0; r < 4; ++r) {
            const int rl = rl0 + r;
            g[r][0]=mus[rl*3]; g[r][1]=mus[rl*3+1]; g[r][2]=mus[rl*3+2];
            g[r][3]=scs[rl*3]; g[r][4]=scs[rl*3+1]; g[r][5]=scs[rl*3+2];
            g[r][6]=rots[rl*4]; g[r][7]=rots[rl*4+1]; g[r][8]=rots[rl*4+2]; g[r][9]=rots[rl*4+3];
        }
        float hv[4][8];
        #pragma unroll
        for (int jj = 0; jj < 8; ++jj) {
            const int d = lane + 32 * jj;
            float w[10];
            #pragma unroll
            for (int i = 0; i < 10; ++i) w[i] = __ldg(w1 + i * 256 + d);
            const float bv = __ldg(b1 + d);
            #pragma unroll
            for (int r = 0; r < 4; ++r) {
                float a = bv;
                #pragma unroll
                for (int i = 0; i < 10; ++i) a = fmaf(g[r][i], w[i], a);
                hv[r][jj] = a;
            }
        }
        float s[4] = {0.f, 0.f, 0.f, 0.f};
        #pragma unroll
        for (int r = 0; r < 4; ++r)
            #pragma unroll
            for (int jj = 0; jj < 8; ++jj) s[r] += hv[r][jj];
        #pragma unroll
        for (int o = 16; o; o >>= 1) {
            #pragma unroll
            for (int r = 0; r < 4; ++r) s[r] += __shfl_xor_sync(0xffffffffu, s[r], o);
        }
        float v[4] = {0.f, 0.f, 0.f, 0.f};
        float mean[4];
        #pragma unroll
        for (int r = 0; r < 4; ++r) {
            mean[r] = s[r] * (1.f/256.f);
            #pragma unroll
            for (int jj = 0; jj < 8; ++jj) { float t = hv[r][jj] - mean[r]; v[r] = fmaf(t, t, v[r]); }
        }
        #pragma unroll
        for (int o = 16; o; o >>= 1) {
            #pragma unroll
            for (int r = 0; r < 4; ++r) v[r] += __shfl_xor_sync(0xffffffffu, v[r], o);
        }
        #pragma unroll
        for (int r = 0; r < 4; ++r) {
            const float inv = rsqrtf(v[r] * (1.f/256.f) + 1e-5f);
            const bool valid = (rowBase + rl0 + r < N);
            #pragma unroll
            for (int jj = 0; jj < 8; ++jj) {
                const int d = lane + 32 * jj;
                float t = (hv[r][jj] - mean[r]) * inv * __ldg(gamma + d) + __ldg(beta + d);
                t = fmaxf(t, 0.f);
                if (!valid) t = 0.f;
                hs[(rl0 + r) * LDH + d] = __float2half(t);
            }
        }
    }
    __syncthreads();

    // ---- phase 2: GEMM, warp tile 64x32, 17 chunks, 3 bufs ----
    const int c0 = wid * 32;

    wmma::fragment<wmma::accumulator, 16,16,16, float> acc[4][2];
    #pragma unroll
    for (int mi = 0; mi < 4; ++mi)
        #pragma unroll
        for (int ni = 0; ni < 2; ++ni) wmma::fill_fragment(acc[mi][ni], 0.f);

    #pragma unroll 1
    for (int t = 0; t < NCHUNK; ++t) {
        if (t + 2 < NCHUNK) { cp_wait<1>(); } else { cp_wait<0>(); }
        __syncthreads();
        if (t + 2 < NCHUNK) { load_chunk(smb, (t + 2) % 3, (t + 2) * 16, tid); cp_commit(); }

        const __half* bhi = (const __half*)(sm + B_F) + (t % 3) * 8448;
        const __half* blo = bhi + 16 * LDB;
        const int kk = t * 16;

        wmma::fragment<wmma::matrix_a, 16,16,16, __half, wmma::row_major> a[4];
        #pragma unroll
        for (int mi = 0; mi < 4; ++mi)
            wmma::load_matrix_sync(a[mi], hs + (mi*16) * LDH + kk, LDH);

        #pragma unroll
        for (int ni = 0; ni < 2; ++ni) {
            wmma::fragment<wmma::matrix_b, 16,16,16, __half, wmma::row_major> bh, bl;
            wmma::load_matrix_sync(bh, bhi + c0 + ni*16, LDB);
            wmma::load_matrix_sync(bl, blo + c0 + ni*16, LDB);
            #pragma unroll
            for (int mi = 0; mi < 4; ++mi) {
                wmma::mma_sync(acc[mi][ni], a[mi], bh, acc[mi][ni]);
                wmma::mma_sync(acc[mi][ni], a[mi], bl, acc[mi][ni]);
            }
        }
    }
    __syncthreads();   // hs + B dead; fs takes over

    // ---- phase 3: acc -> fs ; features = fs + Q -> out + fs ----
    #pragma unroll
    for (int mi = 0; mi < 4; ++mi)
        #pragma unroll
        for (int ni = 0; ni < 2; ++ni)
            wmma::store_matrix_sync(fs + (mi*16) * LDFS + c0 + ni*16,
                                    acc[mi][ni], LDFS, wmma::mem_row_major);
    __syncthreads();

    #pragma unroll 1
    for (int rb = 0; rb < MT; rb += 8) {
        float qv[8];
        #pragma unroll
        for (int k = 0; k < 8; ++k) {
            const int row = rowBase + rb + k;
            qv[k] = (row < N) ? Q[(size_t)row * 256 + tid] : 0.f;
        }
        #pragma unroll
        for (int k = 0; k < 8; ++k) {
            const int row = rowBase + rb + k;
            const float v = fs[(rb + k) * LDFS + tid] + qv[k];
            if (row < N) out[(size_t)row * 256 + tid] = v;
            fs[(rb + k) * LDFS + tid] = v;
        }
    }
    __syncthreads();

    // ---- phase 4: lf matmul + corners + refs (from smem) ----
    const int rl    = wid * 8 + (lane >> 2);
    const int cpart = lane & 3;
    const int row   = rowBase + rl;
    float s[18];
    #pragma unroll
    for (int j = 0; j < 18; ++j) s[j] = 0.f;
    const int cbase = cpart * 64;
    #pragma unroll 1
    for (int u = 0; u < 64; u += 4) {
        float4 fv = *(const float4*)&fs[rl * LDFS + cbase + u];
        const float fvals[4] = {fv.x, fv.y, fv.z, fv.w};
        #pragma unroll
        for (int p = 0; p < 4; ++p) {
            const float f = fvals[p];
            const int c = cbase + u + p;
            const float4 l0 = *(const float4*)&lfws[c*20 + 0];
            const float4 l1 = *(const float4*)&lfws[c*20 + 4];
            const float4 l2 = *(const float4*)&lfws[c*20 + 8];
            const float4 l3 = *(const float4*)&lfws[c*20 + 12];
            const float2 l4 = *(const float2*)&lfws[c*20 + 16];
            s[0]  = fmaf(f, l0.x, s[0]);  s[1]  = fmaf(f, l0.y, s[1]);
            s[2]  = fmaf(f, l0.z, s[2]);  s[3]  = fmaf(f, l0.w, s[3]);
            s[4]  = fmaf(f, l1.x, s[4]);  s[5]  = fmaf(f, l1.y, s[5]);
            s[6]  = fmaf(f, l1.z, s[6]);  s[7]  = fmaf(f, l1.w, s[7]);
            s[8]  = fmaf(f, l2.x, s[8]);  s[9]  = fmaf(f, l2.y, s[9]);
            s[10] = fmaf(f, l2.z, s[10]); s[11] = fmaf(f, l2.w, s[11]);
            s[12] = fmaf(f, l3.x, s[12]); s[13] = fmaf(f, l3.y, s[13]);
            s[14] = fmaf(f, l3.z, s[14]); s[15] = fmaf(f, l3.w, s[15]);
            s[16] = fmaf(f, l4.x, s[16]); s[17] = fmaf(f, l4.y, s[17]);
        }
    }
    #pragma unroll
    for (int j = 0; j < 18; ++j) {
        s[j] += __shfl_xor_sync(0xffffffffu, s[j], 1);
        s[j] += __shfl_xor_sync(0xffffffffu, s[j], 2);
    }

    if (row < N) {
        const float mx = mus[rl*3], my = mus[rl*3+1], mz = mus[rl*3+2];
        const float sx = scs[rl*3]*0.5f, sy = scs[rl*3+1]*0.5f, sz = scs[rl*3+2]*0.5f;
        float qw = rots[rl*4], qx = rots[rl*4+1], qy = rots[rl*4+2], qz = rots[rl*4+3];
        const float nrm = fmaxf(sqrtf(qw*qw + qx*qx + qy*qy + qz*qz), 1e-8f);
        const float inr = 1.f / nrm;
        qw *= inr; qx *= inr; qy *= inr; qz *= inr;
        const float r00 = 1.f - 2.f*(qy*qy + qz*qz), r01 = 2.f*(qx*qy - qz*qw), r02 = 2.f*(qx*qz + qy*qw);
        const float r10 = 2.f*(qx*qy + qz*qw), r11 = 1.f - 2.f*(qx*qx + qz*qz), r12 = 2.f*(qy*qz - qx*qw);
        const float r20 = 2.f*(qx*qz - qy*qw), r21 = 2.f*(qy*qz + qx*qw), r22 = 1.f - 2.f*(qx*qx + qy*qy);

        const size_t OUT_CORN = (size_t)N * 256;
        const size_t OUT_XY   = OUT_CORN + (size_t)N * 33;
        const size_t OUT_XZ   = OUT_XY + (size_t)N * 22;
        const size_t OUT_YZ   = OUT_XZ + (size_t)N * 22;
        const float invxy = 1.f / (102.4f + 1e-6f);
        const float invz  = 1.f / (8.0f + 1e-6f);

        #pragma unroll
        for (int mm = 0; mm < 3; ++mm) {
            const int m = cpart + mm * 4;
            if (m < 11) {
                float lx, ly, lz;
                if (m == 0)      { lx = 0.f;  ly = 0.f;  lz = 0.f; }
                else if (m == 1) { lx = 0.f;  ly = sy;   lz = 0.f; }
                else if (m == 2) { lx = 0.f;  ly = -sy;  lz = 0.f; }
                else if (m == 3) { lx = sx;   ly = 0.f;  lz = 0.f; }
                else if (m == 4) { lx = -sx;  ly = 0.f;  lz = 0.f; }
                else {
                    const int j = (m - 5) * 3;
                    const float t0 = s[j]   + lfbs[j];
                    const float t1 = s[j+1] + lfbs[j+1];
                    const float t2 = s[j+2] + lfbs[j+2];
                    const float g0 = 1.f / (1.f + __expf(-t0));
                    const float g1 = 1.f / (1.f + __expf(-t1));
                    const float g2 = 1.f / (1.f + __expf(-t2));
                    lx = (g0 - 0.5f) * sx;
                    ly = (g1 - 0.5f) * sy;
                    lz = (g2 - 0.5f) * sz;
                }
                const float cxv = r00*lx + r01*ly + r02*lz + mx;
                const float cyv = r10*lx + r11*ly + r12*lz + my;
                const float czv = r20*lx + r21*ly + r22*lz + mz;
                const size_t cb = OUT_CORN + ((size_t)row * 11 + m) * 3;
                out[cb]   = cxv;
                out[cb+1] = cyv;
                out[cb+2] = czv;
                const float nx = fminf(fmaxf((cxv + 51.2f) * invxy, 0.f), 1.f);
                const float ny = fminf(fmaxf((cyv + 51.2f) * invxy, 0.f), 1.f);
                const float nz = fminf(fmaxf((czv + 5.0f)  * invz,  0.f), 1.f);
                const size_t rb2 = (size_t)row * 11 + m;
                out[OUT_XY + rb2*2]     = nx;
                out[OUT_XY + rb2*2 + 1] = ny;
                out[OUT_XZ + rb2*2]     = nx;
                out[OUT_XZ + rb2*2 + 1] = nz;
                out[OUT_YZ + rb2*2]     = ny;
                out[OUT_YZ + rb2*2 + 1] = nz;
            }
        }
    }
}

extern "C" void kernel_launch(void* const* d_in, const int* in_sizes, int n_in,
                              void* d_out, int out_size) {
    const float* mu    = (const float*)d_in[0];
    const float* sc    = (const float*)d_in[1];
    const float* rot   = (const float*)d_in[2];
    const float* Q     = (const float*)d_in[3];
    const float* w1    = (const float*)d_in[4];
    const float* b1    = (const float*)d_in[5];
    const float* gamma = (const float*)d_in[6];
    const float* beta  = (const float*)d_in[7];
    const float* w2    = (const float*)d_in[8];
    const float* b2    = (const float*)d_in[9];
    const float* lfw   = (const float*)d_in[10];
    const float* lfb   = (const float*)d_in[11];
    float* out = (float*)d_out;
    const int N = in_sizes[0] / 3;

    w2_convert_kernel<<<KAUG, 256>>>(w2, b2, lfw);

    const int smem = SMEM_FLOATS * sizeof(float);
    cudaFuncSetAttribute(gauss_fused_kernel,
                         cudaFuncAttributeMaxDynamicSharedMemorySize, smem);
    const int blocks = (N + MT - 1) / MT;
    gauss_fused_kernel<<<blocks, 256, smem>>>(
        mu, sc, rot, Q, w1, b1, gamma, beta, lfb, out, N);
}